// round 4
// baseline (speedup 1.0000x reference)
#include <cuda_runtime.h>
#include <cuda_bf16.h>
#include <cstdint>
#include <cmath>

#define NN   512
#define KK   32
#define PP   1024
#define QQ   512
#define MM   2048
#define RHO        0.70710678118654752f
#define KAPPA_DIAG 0.45f
#define TOL        3e-6f
#define MITR       300

// ---------------- device scratch (no allocation) ----------------
__device__ __align__(128) float g_ZT[MM * NN];
__device__ __align__(128) float g_XT[MM * NN];
__device__ float g_scales[3];

__device__ __align__(128) __nv_bfloat16 g_Uhi[MM * PP];
__device__ __align__(128) __nv_bfloat16 g_Ulo[MM * PP];
__device__ __align__(128) __nv_bfloat16 g_Bhi[NN * PP];
__device__ __align__(128) __nv_bfloat16 g_Blo[NN * PP];
__device__ __align__(128) __nv_bfloat16 g_Chi[QQ * NN];
__device__ __align__(128) __nv_bfloat16 g_Clo[QQ * NN];
__device__ __align__(128) __nv_bfloat16 g_Dhi[QQ * PP];
__device__ __align__(128) __nv_bfloat16 g_Dlo[QQ * PP];
__device__ __align__(128) __nv_bfloat16 g_XThi[MM * NN];
__device__ __align__(128) __nv_bfloat16 g_XTlo[MM * NN];

__device__ __forceinline__ uint32_t smem_u32(const void* p) {
    uint32_t a;
    asm("{ .reg .u64 t; cvta.to.shared.u64 t, %1; cvt.u32.u64 %0, t; }"
        : "=r"(a) : "l"(p));
    return a;
}

__device__ __forceinline__ void ldm_x4(uint32_t& r0, uint32_t& r1,
                                       uint32_t& r2, uint32_t& r3, uint32_t addr) {
    asm volatile("ldmatrix.sync.aligned.m8n8.x4.shared.b16 {%0,%1,%2,%3}, [%4];"
                 : "=r"(r0), "=r"(r1), "=r"(r2), "=r"(r3) : "r"(addr));
}

__device__ __forceinline__ void mma16816(float& c0, float& c1, float& c2, float& c3,
                                         uint32_t a0, uint32_t a1, uint32_t a2, uint32_t a3,
                                         uint32_t b0, uint32_t b1) {
    asm volatile(
        "mma.sync.aligned.m16n8k16.row.col.f32.bf16.bf16.f32 "
        "{%0,%1,%2,%3}, {%4,%5,%6,%7}, {%8,%9}, {%0,%1,%2,%3};"
        : "+f"(c0), "+f"(c1), "+f"(c2), "+f"(c3)
        : "r"(a0), "r"(a1), "r"(a2), "r"(a3), "r"(b0), "r"(b1));
}

// ---------------------------------------------------------------------------
// Kernel 1: projection scale factors (1 CTA, 512 threads)
// ---------------------------------------------------------------------------
__global__ void scales_kernel(const float* __restrict__ L,
                              const float* __restrict__ R,
                              const float* __restrict__ Dg)
{
    __shared__ float red[NN];
    int t = threadIdx.x;

    float s = 0.f;
#pragma unroll
    for (int k = 0; k < KK; ++k) s += fabsf(L[t * KK + k]);
    red[t] = s;
    __syncthreads();
    for (int h = 256; h > 0; h >>= 1) {
        if (t < h) red[t] = fmaxf(red[t], red[t + h]);
        __syncthreads();
    }
    if (t == 0) {
        float nl = red[0];
        g_scales[0] = (nl > RHO) ? (RHO / nl) : 1.0f;
    }
    __syncthreads();

    {
        int k = t & 31, part = t >> 5;
        float cs = 0.f;
        int n0 = part * 32;
        for (int n = n0; n < n0 + 32; ++n) cs += fabsf(R[n * KK + k]);
        red[t] = cs;
    }
    __syncthreads();
    if (t < 32) {
        float cs = 0.f;
#pragma unroll
        for (int p = 0; p < 16; ++p) cs += red[p * 32 + t];
#pragma unroll
        for (int off = 16; off > 0; off >>= 1)
            cs = fmaxf(cs, __shfl_xor_sync(0xffffffffu, cs, off));
        if (t == 0) g_scales[1] = (cs > RHO) ? (RHO / cs) : 1.0f;
    }
    __syncthreads();

    red[t] = fabsf(Dg[t]);
    __syncthreads();
    for (int h = 256; h > 0; h >>= 1) {
        if (t < h) red[t] = fmaxf(red[t], red[t + h]);
        __syncthreads();
    }
    if (t == 0) {
        float dm = red[0];
        g_scales[2] = (dm > KAPPA_DIAG) ? (KAPPA_DIAG / dm) : 1.0f;
    }
}

// ---------------------------------------------------------------------------
// fp32 -> bf16 hi/lo split
// ---------------------------------------------------------------------------
__global__ void split_bf16_kernel(const float* __restrict__ src,
                                  __nv_bfloat16* __restrict__ hi,
                                  __nv_bfloat16* __restrict__ lo, int n4)
{
    int i = blockIdx.x * blockDim.x + threadIdx.x;
    if (i >= n4) return;
    float4 v = *(const float4*)(src + i * 4);
    __nv_bfloat16 h0 = __float2bfloat16(v.x);
    __nv_bfloat16 h1 = __float2bfloat16(v.y);
    __nv_bfloat16 h2 = __float2bfloat16(v.z);
    __nv_bfloat16 h3 = __float2bfloat16(v.w);
    __nv_bfloat16 l0 = __float2bfloat16(v.x - __bfloat162float(h0));
    __nv_bfloat16 l1 = __float2bfloat16(v.y - __bfloat162float(h1));
    __nv_bfloat16 l2 = __float2bfloat16(v.z - __bfloat162float(h2));
    __nv_bfloat16 l3 = __float2bfloat16(v.w - __bfloat162float(h3));
    __nv_bfloat162* hp = (__nv_bfloat162*)(hi + i * 4);
    __nv_bfloat162* lp = (__nv_bfloat162*)(lo + i * 4);
    hp[0] = __nv_bfloat162{h0, h1}; hp[1] = __nv_bfloat162{h2, h3};
    lp[0] = __nv_bfloat162{l0, l1}; lp[1] = __nv_bfloat162{l2, l3};
}

// ---------------------------------------------------------------------------
// HMMA bf16 GEMM: Cm[m][j] = sum over phases sum_k A[m][k]*B[j][k]
// BM=128, BN=64, BK=32, 256 threads (8 warps, 4x2), warp tile 32x32.
// Double-buffered SMEM (padded rows), non-trans ldmatrix for both operands.
// ---------------------------------------------------------------------------
struct GemmParams {
    const __nv_bfloat16* A[6];
    const __nv_bfloat16* B[6];
    int K[6];
};

#define LDS_A 40   // bf16 row stride for 32-col tile (padded)
#define BKC   32

__global__ __launch_bounds__(256)
void gemm_hmma_kernel(GemmParams P, int nph, float* __restrict__ Cm, int ldc)
{
    __shared__ __align__(16) __nv_bfloat16 As[2][128 * LDS_A];
    __shared__ __align__(16) __nv_bfloat16 Bs[2][64 * LDS_A];

    int tid  = threadIdx.x;
    int wid  = tid >> 5;
    int lane = tid & 31;
    int wm   = wid >> 1;     // 0..3  (M)
    int wn   = wid & 1;      // 0..1  (N)
    int bm = blockIdx.x * 128;
    int bn = blockIdx.y * 64;

    int NC = 0;
    for (int i = 0; i < nph; ++i) NC += P.K[i] >> 5;

    // per-thread load indices: A rows tid/4 and tid/4+64, B row tid/4; colgroup tid%4
    int lrow = tid >> 2;
    int lcg  = tid & 3;

    // per-lane ldmatrix offsets
    int lrow16 = lane & 15;
    int lcol8  = (lane >> 4) << 3;
    uint32_t a_base[2], b_base[2];
#pragma unroll
    for (int b = 0; b < 2; ++b) {
        a_base[b] = smem_u32(&As[b][(wm * 32 + lrow16) * LDS_A + lcol8]);
        b_base[b] = smem_u32(&Bs[b][(wn * 32 + lrow16) * LDS_A + lcol8]);
    }

    float acc[2][4][4];
#pragma unroll
    for (int i = 0; i < 2; ++i)
#pragma unroll
        for (int j = 0; j < 4; ++j)
#pragma unroll
            for (int c = 0; c < 4; ++c) acc[i][j][c] = 0.f;

    // prologue: load chunk 0 into buffer 0
    {
        int c = 0, ph = 0;
        while (ph < nph - 1 && c >= (P.K[ph] >> 5)) { c -= P.K[ph] >> 5; ++ph; }
        const __nv_bfloat16* A = P.A[ph];
        const __nv_bfloat16* B = P.B[ph];
        int ld = P.K[ph];
        *(uint4*)&As[0][lrow * LDS_A + lcg * 8] =
            *(const uint4*)(A + (size_t)(bm + lrow) * ld + lcg * 8);
        *(uint4*)&As[0][(lrow + 64) * LDS_A + lcg * 8] =
            *(const uint4*)(A + (size_t)(bm + lrow + 64) * ld + lcg * 8);
        *(uint4*)&Bs[0][lrow * LDS_A + lcg * 8] =
            *(const uint4*)(B + (size_t)(bn + lrow) * ld + lcg * 8);
    }
    __syncthreads();

    for (int g = 0; g < NC; ++g) {
        int b  = g & 1;
        int nb = b ^ 1;

        uint4 ra0, ra1, rb0;
        bool more = (g + 1 < NC);
        if (more) {
            int c = g + 1, ph = 0;
            while (ph < nph - 1 && c >= (P.K[ph] >> 5)) { c -= P.K[ph] >> 5; ++ph; }
            const __nv_bfloat16* A = P.A[ph];
            const __nv_bfloat16* B = P.B[ph];
            int ld = P.K[ph];
            int kt = c << 5;
            ra0 = *(const uint4*)(A + (size_t)(bm + lrow) * ld + kt + lcg * 8);
            ra1 = *(const uint4*)(A + (size_t)(bm + lrow + 64) * ld + kt + lcg * 8);
            rb0 = *(const uint4*)(B + (size_t)(bn + lrow) * ld + kt + lcg * 8);
        }

        // compute on buffer b
#pragma unroll
        for (int kt = 0; kt < 2; ++kt) {
            uint32_t af[2][4];
            ldm_x4(af[0][0], af[0][1], af[0][2], af[0][3],
                   a_base[b] + (kt * 16) * 2);
            ldm_x4(af[1][0], af[1][1], af[1][2], af[1][3],
                   a_base[b] + (16 * LDS_A + kt * 16) * 2);
            uint32_t bf[2][4];   // [np][q]: q0=b0 nt(2np), q1=b0 nt(2np+1), q2=b1 nt(2np), q3=b1 nt(2np+1)
            ldm_x4(bf[0][0], bf[0][1], bf[0][2], bf[0][3],
                   b_base[b] + (kt * 16) * 2);
            ldm_x4(bf[1][0], bf[1][1], bf[1][2], bf[1][3],
                   b_base[b] + (16 * LDS_A + kt * 16) * 2);
#pragma unroll
            for (int mt = 0; mt < 2; ++mt) {
#pragma unroll
                for (int nt = 0; nt < 4; ++nt) {
                    uint32_t bb0 = bf[nt >> 1][(nt & 1)];
                    uint32_t bb1 = bf[nt >> 1][(nt & 1) + 2];
                    mma16816(acc[mt][nt][0], acc[mt][nt][1], acc[mt][nt][2], acc[mt][nt][3],
                             af[mt][0], af[mt][1], af[mt][2], af[mt][3], bb0, bb1);
                }
            }
        }

        if (more) {
            *(uint4*)&As[nb][lrow * LDS_A + lcg * 8] = ra0;
            *(uint4*)&As[nb][(lrow + 64) * LDS_A + lcg * 8] = ra1;
            *(uint4*)&Bs[nb][lrow * LDS_A + lcg * 8] = rb0;
        }
        __syncthreads();
    }

    // epilogue: c0,c1 -> (row lane/4, cols 2*(lane%4)+{0,1}); c2,c3 -> row+8
    int er = lane >> 2;
    int ec = (lane & 3) * 2;
#pragma unroll
    for (int mt = 0; mt < 2; ++mt) {
#pragma unroll
        for (int nt = 0; nt < 4; ++nt) {
            float* dst = Cm + (size_t)(bm + wm * 32 + mt * 16 + er) * ldc
                       + bn + wn * 32 + nt * 8 + ec;
            *(float2*)dst = make_float2(acc[mt][nt][0], acc[mt][nt][1]);
            *(float2*)(dst + 8 * ldc) = make_float2(acc[mt][nt][2], acc[mt][nt][3]);
        }
    }
}

// ---------------------------------------------------------------------------
// Fixed point: per-column Picard  x = relu(s*L(R^T x) + Dp.*x + z)
// ---------------------------------------------------------------------------
__global__ __launch_bounds__(512, 1)
void fixed_point_kernel(const float* __restrict__ L,
                        const float* __restrict__ R,
                        const float* __restrict__ Dg)
{
    extern __shared__ float sm[];
    float* Lt = sm;
    float* Rt = sm + KK * NN;
    float* Dp = sm + 2 * KK * NN;

    int t = threadIdx.x;
    float sD = g_scales[2];
    float s  = g_scales[0] * g_scales[1];

#pragma unroll
    for (int k = 0; k < KK; ++k) {
        Lt[k * NN + t] = L[t * KK + k];
        Rt[k * NN + t] = R[t * KK + k];
    }
    Dp[t] = Dg[t] * sD;
    __syncthreads();

    int lane = t & 31;
    int wid  = t >> 5;
    int m    = blockIdx.x * 16 + wid;

    float x[16], z[16];
#pragma unroll
    for (int i = 0; i < 16; ++i) {
        z[i] = g_ZT[(size_t)m * NN + lane + 32 * i];
        x[i] = 0.f;
    }

    for (int iter = 0; iter < MITR; ++iter) {
        float y[KK];
#pragma unroll
        for (int k = 0; k < KK; ++k) {
            float a = 0.f;
#pragma unroll
            for (int i = 0; i < 16; ++i)
                a = fmaf(Rt[k * NN + lane + 32 * i], x[i], a);
            y[k] = a;
        }
#pragma unroll
        for (int k = 0; k < KK; ++k) {
#pragma unroll
            for (int off = 16; off > 0; off >>= 1)
                y[k] += __shfl_xor_sync(0xffffffffu, y[k], off);
            y[k] *= s;
        }

        float err = 0.f;
#pragma unroll
        for (int i = 0; i < 16; ++i) {
            int n = lane + 32 * i;
            float a = fmaf(Dp[n], x[i], z[i]);
#pragma unroll
            for (int k = 0; k < KK; ++k)
                a = fmaf(Lt[k * NN + n], y[k], a);
            float xn = fmaxf(a, 0.f);
            err = fmaxf(err, fabsf(xn - x[i]));
            x[i] = xn;
        }
#pragma unroll
        for (int off = 16; off > 0; off >>= 1)
            err = fmaxf(err, __shfl_xor_sync(0xffffffffu, err, off));
        if (err < TOL) break;
    }

#pragma unroll
    for (int i = 0; i < 16; ++i)
        g_XT[(size_t)m * NN + lane + 32 * i] = x[i];
}

// ---------------------------------------------------------------------------
extern "C" void kernel_launch(void* const* d_in, const int* in_sizes, int n_in,
                              void* d_out, int out_size)
{
    (void)in_sizes; (void)n_in; (void)out_size;
    const float* U  = (const float*)d_in[0];
    const float* L  = (const float*)d_in[1];
    const float* R  = (const float*)d_in[2];
    const float* Dg = (const float*)d_in[3];
    const float* B  = (const float*)d_in[4];
    const float* C  = (const float*)d_in[5];
    const float* D  = (const float*)d_in[6];
    float* out = (float*)d_out;

    static int attr_set = 0;
    if (!attr_set) {
        cudaFuncSetAttribute(fixed_point_kernel,
                             cudaFuncAttributeMaxDynamicSharedMemorySize,
                             (2 * KK * NN + NN) * sizeof(float));
        attr_set = 1;
    }

    float* zt;  cudaGetSymbolAddress((void**)&zt,  g_ZT);
    float* xt;  cudaGetSymbolAddress((void**)&xt,  g_XT);
    __nv_bfloat16 *uhi, *ulo, *bhi, *blo, *chi, *clo, *dhi, *dlo, *xhi, *xlo;
    cudaGetSymbolAddress((void**)&uhi, g_Uhi); cudaGetSymbolAddress((void**)&ulo, g_Ulo);
    cudaGetSymbolAddress((void**)&bhi, g_Bhi); cudaGetSymbolAddress((void**)&blo, g_Blo);
    cudaGetSymbolAddress((void**)&chi, g_Chi); cudaGetSymbolAddress((void**)&clo, g_Clo);
    cudaGetSymbolAddress((void**)&dhi, g_Dhi); cudaGetSymbolAddress((void**)&dlo, g_Dlo);
    cudaGetSymbolAddress((void**)&xhi, g_XThi); cudaGetSymbolAddress((void**)&xlo, g_XTlo);

    scales_kernel<<<1, 512>>>(L, R, Dg);

    split_bf16_kernel<<<(MM * PP / 4 + 255) / 256, 256>>>(U, uhi, ulo, MM * PP / 4);
    split_bf16_kernel<<<(NN * PP / 4 + 255) / 256, 256>>>(B, bhi, blo, NN * PP / 4);
    split_bf16_kernel<<<(QQ * NN / 4 + 255) / 256, 256>>>(C, chi, clo, QQ * NN / 4);
    split_bf16_kernel<<<(QQ * PP / 4 + 255) / 256, 256>>>(D, dhi, dlo, QQ * PP / 4);

    // ZT = U @ B^T  (hi*hi + lo*hi + hi*lo)
    {
        GemmParams P{};
        P.A[0] = uhi; P.B[0] = bhi; P.K[0] = PP;
        P.A[1] = ulo; P.B[1] = bhi; P.K[1] = PP;
        P.A[2] = uhi; P.B[2] = blo; P.K[2] = PP;
        gemm_hmma_kernel<<<dim3(MM / 128, NN / 64), 256>>>(P, 3, zt, NN);
    }

    fixed_point_kernel<<<MM / 16, 512, (2 * KK * NN + NN) * sizeof(float)>>>(L, R, Dg);

    split_bf16_kernel<<<(MM * NN / 4 + 255) / 256, 256>>>(xt, xhi, xlo, MM * NN / 4);

    // out = XT @ C^T + U @ D^T  (6 phases)
    {
        GemmParams P{};
        P.A[0] = xhi; P.B[0] = chi; P.K[0] = NN;
        P.A[1] = xlo; P.B[1] = chi; P.K[1] = NN;
        P.A[2] = xhi; P.B[2] = clo; P.K[2] = NN;
        P.A[3] = uhi; P.B[3] = dhi; P.K[3] = PP;
        P.A[4] = ulo; P.B[4] = dhi; P.K[4] = PP;
        P.A[5] = uhi; P.B[5] = dlo; P.K[5] = PP;
        gemm_hmma_kernel<<<dim3(MM / 128, QQ / 64), 256>>>(P, 6, out, QQ);
    }
}

// round 5
// speedup vs baseline: 1.9451x; 1.9451x over previous
#include <cuda_runtime.h>
#include <cuda_bf16.h>
#include <cstdint>
#include <cmath>

#define NN   512
#define KK   32
#define PP   1024
#define QQ   512
#define MM   2048
#define RHO        0.70710678118654752f
#define KAPPA_DIAG 0.45f
#define TOL        3e-6f
#define MITR       300

// ---------------- device scratch (no allocation) ----------------
__device__ __align__(128) float g_ZT[MM * NN];
__device__ float g_scales[3];

__device__ __align__(128) __nv_bfloat16 g_Uhi[MM * PP];
__device__ __align__(128) __nv_bfloat16 g_Ulo[MM * PP];
__device__ __align__(128) __nv_bfloat16 g_Bhi[NN * PP];
__device__ __align__(128) __nv_bfloat16 g_Chi[QQ * NN];
__device__ __align__(128) __nv_bfloat16 g_Dhi[QQ * PP];
__device__ __align__(128) __nv_bfloat16 g_Dlo[QQ * PP];
__device__ __align__(128) __nv_bfloat16 g_XThi[MM * NN];

__device__ __forceinline__ uint32_t smem_u32(const void* p) {
    uint32_t a;
    asm("{ .reg .u64 t; cvta.to.shared.u64 t, %1; cvt.u32.u64 %0, t; }"
        : "=r"(a) : "l"(p));
    return a;
}

__device__ __forceinline__ void ldm_x4(uint32_t& r0, uint32_t& r1,
                                       uint32_t& r2, uint32_t& r3, uint32_t addr) {
    asm volatile("ldmatrix.sync.aligned.m8n8.x4.shared.b16 {%0,%1,%2,%3}, [%4];"
                 : "=r"(r0), "=r"(r1), "=r"(r2), "=r"(r3) : "r"(addr));
}

__device__ __forceinline__ void mma16816(float& c0, float& c1, float& c2, float& c3,
                                         uint32_t a0, uint32_t a1, uint32_t a2, uint32_t a3,
                                         uint32_t b0, uint32_t b1) {
    asm volatile(
        "mma.sync.aligned.m16n8k16.row.col.f32.bf16.bf16.f32 "
        "{%0,%1,%2,%3}, {%4,%5,%6,%7}, {%8,%9}, {%0,%1,%2,%3};"
        : "+f"(c0), "+f"(c1), "+f"(c2), "+f"(c3)
        : "r"(a0), "r"(a1), "r"(a2), "r"(a3), "r"(b0), "r"(b1));
}

#define CP16(dst, src) \
    asm volatile("cp.async.cg.shared.global [%0], [%1], 16;" :: "r"(dst), "l"(src))
#define CP_COMMIT() asm volatile("cp.async.commit_group;" ::: "memory")
#define CP_WAIT2()  asm volatile("cp.async.wait_group 2;" ::: "memory")

// ---------------------------------------------------------------------------
// Kernel 1: projection scale factors (1 CTA, 512 threads)
// ---------------------------------------------------------------------------
__global__ void scales_kernel(const float* __restrict__ L,
                              const float* __restrict__ R,
                              const float* __restrict__ Dg)
{
    __shared__ float red[NN];
    int t = threadIdx.x;

    float s = 0.f;
#pragma unroll
    for (int k = 0; k < KK; ++k) s += fabsf(L[t * KK + k]);
    red[t] = s;
    __syncthreads();
    for (int h = 256; h > 0; h >>= 1) {
        if (t < h) red[t] = fmaxf(red[t], red[t + h]);
        __syncthreads();
    }
    if (t == 0) {
        float nl = red[0];
        g_scales[0] = (nl > RHO) ? (RHO / nl) : 1.0f;
    }
    __syncthreads();

    {
        int k = t & 31, part = t >> 5;
        float cs = 0.f;
        int n0 = part * 32;
        for (int n = n0; n < n0 + 32; ++n) cs += fabsf(R[n * KK + k]);
        red[t] = cs;
    }
    __syncthreads();
    if (t < 32) {
        float cs = 0.f;
#pragma unroll
        for (int p = 0; p < 16; ++p) cs += red[p * 32 + t];
#pragma unroll
        for (int off = 16; off > 0; off >>= 1)
            cs = fmaxf(cs, __shfl_xor_sync(0xffffffffu, cs, off));
        if (t == 0) g_scales[1] = (cs > RHO) ? (RHO / cs) : 1.0f;
    }
    __syncthreads();

    red[t] = fabsf(Dg[t]);
    __syncthreads();
    for (int h = 256; h > 0; h >>= 1) {
        if (t < h) red[t] = fmaxf(red[t], red[t + h]);
        __syncthreads();
    }
    if (t == 0) {
        float dm = red[0];
        g_scales[2] = (dm > KAPPA_DIAG) ? (KAPPA_DIAG / dm) : 1.0f;
    }
}

// ---------------------------------------------------------------------------
// fp32 -> bf16 splits
// ---------------------------------------------------------------------------
__global__ void split_hilo_kernel(const float* __restrict__ src,
                                  __nv_bfloat16* __restrict__ hi,
                                  __nv_bfloat16* __restrict__ lo, int n4)
{
    int i = blockIdx.x * blockDim.x + threadIdx.x;
    if (i >= n4) return;
    float4 v = *(const float4*)(src + i * 4);
    __nv_bfloat16 h0 = __float2bfloat16(v.x);
    __nv_bfloat16 h1 = __float2bfloat16(v.y);
    __nv_bfloat16 h2 = __float2bfloat16(v.z);
    __nv_bfloat16 h3 = __float2bfloat16(v.w);
    __nv_bfloat16 l0 = __float2bfloat16(v.x - __bfloat162float(h0));
    __nv_bfloat16 l1 = __float2bfloat16(v.y - __bfloat162float(h1));
    __nv_bfloat16 l2 = __float2bfloat16(v.z - __bfloat162float(h2));
    __nv_bfloat16 l3 = __float2bfloat16(v.w - __bfloat162float(h3));
    __nv_bfloat162* hp = (__nv_bfloat162*)(hi + i * 4);
    __nv_bfloat162* lp = (__nv_bfloat162*)(lo + i * 4);
    hp[0] = __nv_bfloat162{h0, h1}; hp[1] = __nv_bfloat162{h2, h3};
    lp[0] = __nv_bfloat162{l0, l1}; lp[1] = __nv_bfloat162{l2, l3};
}

__global__ void split_hi_kernel(const float* __restrict__ src,
                                __nv_bfloat16* __restrict__ hi, int n4)
{
    int i = blockIdx.x * blockDim.x + threadIdx.x;
    if (i >= n4) return;
    float4 v = *(const float4*)(src + i * 4);
    __nv_bfloat162* hp = (__nv_bfloat162*)(hi + i * 4);
    hp[0] = __nv_bfloat162{__float2bfloat16(v.x), __float2bfloat16(v.y)};
    hp[1] = __nv_bfloat162{__float2bfloat16(v.z), __float2bfloat16(v.w)};
}

// ---------------------------------------------------------------------------
// HMMA bf16 GEMM, cp.async 4-stage pipeline.
// BM=128, BN=64, BK=64, 256 threads (8 warps, 4x2), warp tile 32x32.
// Cm[m][j] = sum over phases sum_k A[m][k]*B[j][k]
// ---------------------------------------------------------------------------
struct GemmParams {
    const __nv_bfloat16* A[4];
    const __nv_bfloat16* B[4];
    int K[4];    // multiples of 64; also row stride
};

#define LDAB  72                      // bf16 row stride
#define A_SZB (128 * LDAB * 2)        // 18432 B
#define B_SZB (64 * LDAB * 2)         // 9216 B
#define STG_B (A_SZB + B_SZB)         // 27648 B
#define GEMM_SMEM (4 * STG_B)         // 110592 B

__device__ __forceinline__ void gemm_issue(const GemmParams& P, int nph, int chunk,
                                           uint32_t sA, uint32_t sB,
                                           int bm, int bn, int tid)
{
    int c = chunk, ph = 0;
    while (ph < nph - 1 && c >= (P.K[ph] >> 6)) { c -= P.K[ph] >> 6; ++ph; }
    const __nv_bfloat16* A = P.A[ph];
    const __nv_bfloat16* B = P.B[ph];
    int ld = P.K[ph];
    int kt = c << 6;
#pragma unroll
    for (int i = 0; i < 4; ++i) {
        int idx = tid + 256 * i;
        int row = idx >> 3, c16 = idx & 7;
        CP16(sA + (row * LDAB + c16 * 8) * 2,
             A + (size_t)(bm + row) * ld + kt + c16 * 8);
    }
#pragma unroll
    for (int i = 0; i < 2; ++i) {
        int idx = tid + 256 * i;
        int row = idx >> 3, c16 = idx & 7;
        CP16(sB + (row * LDAB + c16 * 8) * 2,
             B + (size_t)(bn + row) * ld + kt + c16 * 8);
    }
}

__global__ __launch_bounds__(256, 1)
void gemm_hmma_kernel(GemmParams P, int nph, float* __restrict__ Cm, int ldc)
{
    extern __shared__ char gsm[];
    int tid  = threadIdx.x;
    int wid  = tid >> 5;
    int lane = tid & 31;
    int wm   = wid >> 1;
    int wn   = wid & 1;
    int bm = blockIdx.x * 128;
    int bn = blockIdx.y * 64;

    int NC = 0;
#pragma unroll
    for (int i = 0; i < 4; ++i) if (i < nph) NC += P.K[i] >> 6;

    uint32_t smb = smem_u32(gsm);
    int lrow16 = lane & 15;
    int lcol8  = (lane >> 4) << 3;
    uint32_t a_off = ((wm * 32 + lrow16) * LDAB + lcol8) * 2;
    uint32_t b_off = ((wn * 32 + lrow16) * LDAB + lcol8) * 2;

    float acc[2][4][4];
#pragma unroll
    for (int i = 0; i < 2; ++i)
#pragma unroll
        for (int j = 0; j < 4; ++j)
#pragma unroll
            for (int c = 0; c < 4; ++c) acc[i][j][c] = 0.f;

    // prologue: 3 stages in flight
#pragma unroll
    for (int s = 0; s < 3; ++s) {
        if (s < NC)
            gemm_issue(P, nph, s, smb + s * STG_B, smb + s * STG_B + A_SZB, bm, bn, tid);
        CP_COMMIT();
    }

    for (int g = 0; g < NC; ++g) {
        CP_WAIT2();
        __syncthreads();
        int st = g & 3;
        uint32_t a_base = smb + st * STG_B + a_off;
        uint32_t b_base = smb + st * STG_B + A_SZB + b_off;
#pragma unroll
        for (int kt = 0; kt < 4; ++kt) {
            uint32_t af[2][4];
            ldm_x4(af[0][0], af[0][1], af[0][2], af[0][3], a_base + kt * 32);
            ldm_x4(af[1][0], af[1][1], af[1][2], af[1][3],
                   a_base + 16 * LDAB * 2 + kt * 32);
            uint32_t bf[2][4];
            ldm_x4(bf[0][0], bf[0][1], bf[0][2], bf[0][3], b_base + kt * 32);
            ldm_x4(bf[1][0], bf[1][1], bf[1][2], bf[1][3],
                   b_base + 16 * LDAB * 2 + kt * 32);
#pragma unroll
            for (int mt = 0; mt < 2; ++mt)
#pragma unroll
                for (int nt = 0; nt < 4; ++nt) {
                    uint32_t bb0 = bf[nt >> 1][(nt & 1)];
                    uint32_t bb1 = bf[nt >> 1][(nt & 1) + 2];
                    mma16816(acc[mt][nt][0], acc[mt][nt][1],
                             acc[mt][nt][2], acc[mt][nt][3],
                             af[mt][0], af[mt][1], af[mt][2], af[mt][3], bb0, bb1);
                }
        }
        int nx = g + 3;
        if (nx < NC) {
            int ns = nx & 3;
            gemm_issue(P, nph, nx, smb + ns * STG_B, smb + ns * STG_B + A_SZB, bm, bn, tid);
        }
        CP_COMMIT();   // empty group ok near tail
    }

    int er = lane >> 2;
    int ec = (lane & 3) * 2;
#pragma unroll
    for (int mt = 0; mt < 2; ++mt)
#pragma unroll
        for (int nt = 0; nt < 4; ++nt) {
            float* dst = Cm + (size_t)(bm + wm * 32 + mt * 16 + er) * ldc
                       + bn + wn * 32 + nt * 8 + ec;
            *(float2*)dst = make_float2(acc[mt][nt][0], acc[mt][nt][1]);
            *(float2*)(dst + 8 * ldc) = make_float2(acc[mt][nt][2], acc[mt][nt][3]);
        }
}

// ---------------------------------------------------------------------------
// Fixed point: x = relu(s*L(R^T x) + Dp.*x + z), one column per warp.
// L,R in SMEM row-major [n][k] with stride 36 (conflict-free float4).
// Writes XThi (bf16) directly.
// ---------------------------------------------------------------------------
#define FP_SMEM ((2 * NN * 36 + NN) * 4)

__global__ __launch_bounds__(512, 1)
void fixed_point_kernel(const float* __restrict__ L,
                        const float* __restrict__ R,
                        const float* __restrict__ Dg,
                        __nv_bfloat16* __restrict__ XThi)
{
    extern __shared__ float fsm[];
    float* Ls = fsm;                 // [512][36]
    float* Rs = fsm + NN * 36;
    float* Dp = fsm + 2 * NN * 36;

    int t = threadIdx.x;
    float sD = g_scales[2];
    float s  = g_scales[0] * g_scales[1];

#pragma unroll
    for (int i = 0; i < 32; ++i) {
        int idx = i * 512 + t;
        int n = idx >> 5, k = idx & 31;
        Ls[n * 36 + k] = L[idx];
        Rs[n * 36 + k] = R[idx];
    }
    Dp[t] = Dg[t] * sD;
    __syncthreads();

    int lane = t & 31;
    int wid  = t >> 5;
    int m    = blockIdx.x * 16 + wid;

    float x[16], z[16];
#pragma unroll
    for (int i = 0; i < 16; ++i) {
        z[i] = g_ZT[(size_t)m * NN + lane + 32 * i];
        x[i] = 0.f;
    }

    for (int iter = 0; iter < MITR; ++iter) {
        float y[32];
#pragma unroll
        for (int k = 0; k < 32; ++k) y[k] = 0.f;
#pragma unroll
        for (int i = 0; i < 16; ++i) {
            const float* rp = Rs + (lane + 32 * i) * 36;
            float xi = x[i];
#pragma unroll
            for (int k4 = 0; k4 < 8; ++k4) {
                float4 r = *(const float4*)(rp + k4 * 4);
                y[k4 * 4 + 0] = fmaf(r.x, xi, y[k4 * 4 + 0]);
                y[k4 * 4 + 1] = fmaf(r.y, xi, y[k4 * 4 + 1]);
                y[k4 * 4 + 2] = fmaf(r.z, xi, y[k4 * 4 + 2]);
                y[k4 * 4 + 3] = fmaf(r.w, xi, y[k4 * 4 + 3]);
            }
        }
#pragma unroll
        for (int k = 0; k < 32; ++k) {
#pragma unroll
            for (int off = 16; off > 0; off >>= 1)
                y[k] += __shfl_xor_sync(0xffffffffu, y[k], off);
            y[k] *= s;
        }

        float err = 0.f;
#pragma unroll
        for (int i = 0; i < 16; ++i) {
            int n = lane + 32 * i;
            float a = fmaf(Dp[n], x[i], z[i]);
            const float* lp = Ls + n * 36;
#pragma unroll
            for (int k4 = 0; k4 < 8; ++k4) {
                float4 l = *(const float4*)(lp + k4 * 4);
                a = fmaf(l.x, y[k4 * 4 + 0], a);
                a = fmaf(l.y, y[k4 * 4 + 1], a);
                a = fmaf(l.z, y[k4 * 4 + 2], a);
                a = fmaf(l.w, y[k4 * 4 + 3], a);
            }
            float xn = fmaxf(a, 0.f);
            err = fmaxf(err, fabsf(xn - x[i]));
            x[i] = xn;
        }
#pragma unroll
        for (int off = 16; off > 0; off >>= 1)
            err = fmaxf(err, __shfl_xor_sync(0xffffffffu, err, off));
        if (err < TOL) break;
    }

#pragma unroll
    for (int i = 0; i < 16; ++i)
        XThi[(size_t)m * NN + lane + 32 * i] = __float2bfloat16(x[i]);
}

// ---------------------------------------------------------------------------
extern "C" void kernel_launch(void* const* d_in, const int* in_sizes, int n_in,
                              void* d_out, int out_size)
{
    (void)in_sizes; (void)n_in; (void)out_size;
    const float* U  = (const float*)d_in[0];
    const float* L  = (const float*)d_in[1];
    const float* R  = (const float*)d_in[2];
    const float* Dg = (const float*)d_in[3];
    const float* B  = (const float*)d_in[4];
    const float* C  = (const float*)d_in[5];
    const float* D  = (const float*)d_in[6];
    float* out = (float*)d_out;

    static int attr_set = 0;
    if (!attr_set) {
        cudaFuncSetAttribute(fixed_point_kernel,
                             cudaFuncAttributeMaxDynamicSharedMemorySize, FP_SMEM);
        cudaFuncSetAttribute(gemm_hmma_kernel,
                             cudaFuncAttributeMaxDynamicSharedMemorySize, GEMM_SMEM);
        attr_set = 1;
    }

    float* zt;  cudaGetSymbolAddress((void**)&zt,  g_ZT);
    __nv_bfloat16 *uhi, *ulo, *bhi, *chi, *dhi, *dlo, *xhi;
    cudaGetSymbolAddress((void**)&uhi, g_Uhi);
    cudaGetSymbolAddress((void**)&ulo, g_Ulo);
    cudaGetSymbolAddress((void**)&bhi, g_Bhi);
    cudaGetSymbolAddress((void**)&chi, g_Chi);
    cudaGetSymbolAddress((void**)&dhi, g_Dhi);
    cudaGetSymbolAddress((void**)&dlo, g_Dlo);
    cudaGetSymbolAddress((void**)&xhi, g_XThi);

    scales_kernel<<<1, 512>>>(L, R, Dg);

    split_hilo_kernel<<<(MM * PP / 4 + 255) / 256, 256>>>(U, uhi, ulo, MM * PP / 4);
    split_hilo_kernel<<<(QQ * PP / 4 + 255) / 256, 256>>>(D, dhi, dlo, QQ * PP / 4);
    split_hi_kernel<<<(NN * PP / 4 + 255) / 256, 256>>>(B, bhi, NN * PP / 4);
    split_hi_kernel<<<(QQ * NN / 4 + 255) / 256, 256>>>(C, chi, QQ * NN / 4);

    // ZT = Uhi @ Bhi^T   (single bf16 term; error attenuated ~22x through C)
    {
        GemmParams P{};
        P.A[0] = uhi; P.B[0] = bhi; P.K[0] = PP;
        gemm_hmma_kernel<<<dim3(MM / 128, NN / 64), 256, GEMM_SMEM>>>(P, 1, zt, NN);
    }

    fixed_point_kernel<<<MM / 16, 512, FP_SMEM>>>(L, R, Dg, xhi);

    // out = XThi @ Chi^T + U @ D^T (3-term on the dominant U@D^T)
    {
        GemmParams P{};
        P.A[0] = xhi; P.B[0] = chi; P.K[0] = NN;
        P.A[1] = uhi; P.B[1] = dhi; P.K[1] = PP;
        P.A[2] = ulo; P.B[2] = dhi; P.K[2] = PP;
        P.A[3] = uhi; P.B[3] = dlo; P.K[3] = PP;
        gemm_hmma_kernel<<<dim3(MM / 128, QQ / 64), 256, GEMM_SMEM>>>(P, 4, out, QQ);
    }
}

// round 6
// speedup vs baseline: 3.9893x; 2.0510x over previous
#include <cuda_runtime.h>
#include <cuda_bf16.h>
#include <cstdint>
#include <cmath>

#define NN   512
#define KK   32
#define PP   1024
#define QQ   512
#define MM   2048
#define RHO        0.70710678118654752f
#define KAPPA_DIAG 0.45f
#define TOL        3e-6f
#define MITR       300

// ---------------- device scratch (no allocation) ----------------
__device__ __align__(128) float g_ZT[MM * NN];
__device__ float g_scales[3];

__device__ __align__(128) __nv_bfloat16 g_Uhi[MM * PP];
__device__ __align__(128) __nv_bfloat16 g_Ulo[MM * PP];
__device__ __align__(128) __nv_bfloat16 g_Bhi[NN * PP];
__device__ __align__(128) __nv_bfloat16 g_Chi[QQ * NN];
__device__ __align__(128) __nv_bfloat16 g_Dhi[QQ * PP];
__device__ __align__(128) __nv_bfloat16 g_Dlo[QQ * PP];
__device__ __align__(128) __nv_bfloat16 g_XThi[MM * NN];

__device__ __forceinline__ uint32_t smem_u32(const void* p) {
    uint32_t a;
    asm("{ .reg .u64 t; cvta.to.shared.u64 t, %1; cvt.u32.u64 %0, t; }"
        : "=r"(a) : "l"(p));
    return a;
}

__device__ __forceinline__ void ldm_x4(uint32_t& r0, uint32_t& r1,
                                       uint32_t& r2, uint32_t& r3, uint32_t addr) {
    asm volatile("ldmatrix.sync.aligned.m8n8.x4.shared.b16 {%0,%1,%2,%3}, [%4];"
                 : "=r"(r0), "=r"(r1), "=r"(r2), "=r"(r3) : "r"(addr));
}

__device__ __forceinline__ void mma16816(float& c0, float& c1, float& c2, float& c3,
                                         uint32_t a0, uint32_t a1, uint32_t a2, uint32_t a3,
                                         uint32_t b0, uint32_t b1) {
    asm volatile(
        "mma.sync.aligned.m16n8k16.row.col.f32.bf16.bf16.f32 "
        "{%0,%1,%2,%3}, {%4,%5,%6,%7}, {%8,%9}, {%0,%1,%2,%3};"
        : "+f"(c0), "+f"(c1), "+f"(c2), "+f"(c3)
        : "r"(a0), "r"(a1), "r"(a2), "r"(a3), "r"(b0), "r"(b1));
}

#define CP16(dst, src) \
    asm volatile("cp.async.cg.shared.global [%0], [%1], 16;" :: "r"(dst), "l"(src))
#define CP_COMMIT() asm volatile("cp.async.commit_group;" ::: "memory")
#define CP_WAIT2()  asm volatile("cp.async.wait_group 2;" ::: "memory")

// ---------------------------------------------------------------------------
// Kernel 1: projection scale factors (1 CTA, 512 threads)
// ---------------------------------------------------------------------------
__global__ void scales_kernel(const float* __restrict__ L,
                              const float* __restrict__ R,
                              const float* __restrict__ Dg)
{
    __shared__ float red[NN];
    int t = threadIdx.x;

    float s = 0.f;
#pragma unroll
    for (int k = 0; k < KK; ++k) s += fabsf(L[t * KK + k]);
    red[t] = s;
    __syncthreads();
    for (int h = 256; h > 0; h >>= 1) {
        if (t < h) red[t] = fmaxf(red[t], red[t + h]);
        __syncthreads();
    }
    if (t == 0) {
        float nl = red[0];
        g_scales[0] = (nl > RHO) ? (RHO / nl) : 1.0f;
    }
    __syncthreads();

    {
        int k = t & 31, part = t >> 5;
        float cs = 0.f;
        int n0 = part * 32;
        for (int n = n0; n < n0 + 32; ++n) cs += fabsf(R[n * KK + k]);
        red[t] = cs;
    }
    __syncthreads();
    if (t < 32) {
        float cs = 0.f;
#pragma unroll
        for (int p = 0; p < 16; ++p) cs += red[p * 32 + t];
#pragma unroll
        for (int off = 16; off > 0; off >>= 1)
            cs = fmaxf(cs, __shfl_xor_sync(0xffffffffu, cs, off));
        if (t == 0) g_scales[1] = (cs > RHO) ? (RHO / cs) : 1.0f;
    }
    __syncthreads();

    red[t] = fabsf(Dg[t]);
    __syncthreads();
    for (int h = 256; h > 0; h >>= 1) {
        if (t < h) red[t] = fmaxf(red[t], red[t + h]);
        __syncthreads();
    }
    if (t == 0) {
        float dm = red[0];
        g_scales[2] = (dm > KAPPA_DIAG) ? (KAPPA_DIAG / dm) : 1.0f;
    }
}

// ---------------------------------------------------------------------------
// One fused split kernel: U,D -> hi+lo ; B,C -> hi
// ---------------------------------------------------------------------------
#define UB4 (MM * PP / 4)   // 524288 -> 2048 blocks
#define DB4 (QQ * PP / 4)   // 131072 -> 512
#define BB4 (NN * PP / 4)   // 131072 -> 512
#define CB4 (QQ * NN / 4)   //  65536 -> 256

__device__ __forceinline__ void do_hilo(const float* src, __nv_bfloat16* hi,
                                        __nv_bfloat16* lo, int i) {
    float4 v = *(const float4*)(src + (size_t)i * 4);
    __nv_bfloat16 h0 = __float2bfloat16(v.x);
    __nv_bfloat16 h1 = __float2bfloat16(v.y);
    __nv_bfloat16 h2 = __float2bfloat16(v.z);
    __nv_bfloat16 h3 = __float2bfloat16(v.w);
    __nv_bfloat162* hp = (__nv_bfloat162*)(hi + (size_t)i * 4);
    __nv_bfloat162* lp = (__nv_bfloat162*)(lo + (size_t)i * 4);
    hp[0] = __nv_bfloat162{h0, h1}; hp[1] = __nv_bfloat162{h2, h3};
    lp[0] = __nv_bfloat162{__float2bfloat16(v.x - __bfloat162float(h0)),
                           __float2bfloat16(v.y - __bfloat162float(h1))};
    lp[1] = __nv_bfloat162{__float2bfloat16(v.z - __bfloat162float(h2)),
                           __float2bfloat16(v.w - __bfloat162float(h3))};
}

__device__ __forceinline__ void do_hi(const float* src, __nv_bfloat16* hi, int i) {
    float4 v = *(const float4*)(src + (size_t)i * 4);
    __nv_bfloat162* hp = (__nv_bfloat162*)(hi + (size_t)i * 4);
    hp[0] = __nv_bfloat162{__float2bfloat16(v.x), __float2bfloat16(v.y)};
    hp[1] = __nv_bfloat162{__float2bfloat16(v.z), __float2bfloat16(v.w)};
}

__global__ void split_all_kernel(const float* __restrict__ U, const float* __restrict__ D,
                                 const float* __restrict__ B, const float* __restrict__ C,
                                 __nv_bfloat16* uhi, __nv_bfloat16* ulo,
                                 __nv_bfloat16* dhi, __nv_bfloat16* dlo,
                                 __nv_bfloat16* bhi, __nv_bfloat16* chi)
{
    int b = blockIdx.x, t = threadIdx.x;
    if (b < 2048)       do_hilo(U, uhi, ulo, b * 256 + t);
    else if (b < 2560)  do_hilo(D, dhi, dlo, (b - 2048) * 256 + t);
    else if (b < 3072)  do_hi(B, bhi, (b - 2560) * 256 + t);
    else                do_hi(C, chi, (b - 3072) * 256 + t);
}

// ---------------------------------------------------------------------------
// HMMA bf16 GEMM, 64x64x64 tiles, 128 threads (4 warps, 2x2), 4-stage cp.async.
// 2 CTAs/SM. Cm[m][j] = sum over phases sum_k A[m][k]*B[j][k]
// ---------------------------------------------------------------------------
struct GemmParams {
    const __nv_bfloat16* A[4];
    const __nv_bfloat16* B[4];
    int K[4];    // multiples of 64; also row stride
};

#define LDAB  72                      // bf16 row stride (144B, ldmatrix conflict-free)
#define T_SZB (64 * LDAB * 2)         // 9216 B per operand tile
#define STG_B (2 * T_SZB)             // 18432 B per stage
#define GEMM_SMEM (4 * STG_B)         // 73728 B

__device__ __forceinline__ void gemm_issue(const GemmParams& P, int nph, int chunk,
                                           uint32_t stg, int bm, int bn, int tid)
{
    int c = chunk, ph = 0;
    while (ph < nph - 1 && c >= (P.K[ph] >> 6)) { c -= P.K[ph] >> 6; ++ph; }
    const __nv_bfloat16* A = P.A[ph];
    const __nv_bfloat16* B = P.B[ph];
    int ld = P.K[ph];
    int kt = c << 6;
#pragma unroll
    for (int i = 0; i < 4; ++i) {
        int idx = tid + 128 * i;
        int row = idx >> 3, c16 = idx & 7;
        CP16(stg + (row * LDAB + c16 * 8) * 2,
             A + (size_t)(bm + row) * ld + kt + c16 * 8);
    }
#pragma unroll
    for (int i = 0; i < 4; ++i) {
        int idx = tid + 128 * i;
        int row = idx >> 3, c16 = idx & 7;
        CP16(stg + T_SZB + (row * LDAB + c16 * 8) * 2,
             B + (size_t)(bn + row) * ld + kt + c16 * 8);
    }
}

__global__ __launch_bounds__(128)
void gemm_hmma_kernel(GemmParams P, int nph, float* __restrict__ Cm, int ldc)
{
    extern __shared__ char gsm[];
    int tid  = threadIdx.x;
    int wid  = tid >> 5;
    int lane = tid & 31;
    int wm   = wid >> 1;   // 0..1
    int wn   = wid & 1;    // 0..1
    int bm = blockIdx.x * 64;
    int bn = blockIdx.y * 64;

    int NC = 0;
#pragma unroll
    for (int i = 0; i < 4; ++i) if (i < nph) NC += P.K[i] >> 6;

    uint32_t smb = smem_u32(gsm);
    int lrow16 = lane & 15;
    int lcol8  = (lane >> 4) << 3;
    uint32_t a_off = ((wm * 32 + lrow16) * LDAB + lcol8) * 2;
    uint32_t b_off = T_SZB + ((wn * 32 + lrow16) * LDAB + lcol8) * 2;

    float acc[2][4][4];
#pragma unroll
    for (int i = 0; i < 2; ++i)
#pragma unroll
        for (int j = 0; j < 4; ++j)
#pragma unroll
            for (int c = 0; c < 4; ++c) acc[i][j][c] = 0.f;

    // prologue: 3 stages in flight
#pragma unroll
    for (int s = 0; s < 3; ++s) {
        if (s < NC) gemm_issue(P, nph, s, smb + s * STG_B, bm, bn, tid);
        CP_COMMIT();
    }

    for (int g = 0; g < NC; ++g) {
        CP_WAIT2();
        __syncthreads();
        int st = g & 3;
        uint32_t a_base = smb + st * STG_B + a_off;
        uint32_t b_base = smb + st * STG_B + b_off;
#pragma unroll
        for (int kt = 0; kt < 4; ++kt) {
            uint32_t af[2][4];
            ldm_x4(af[0][0], af[0][1], af[0][2], af[0][3], a_base + kt * 32);
            ldm_x4(af[1][0], af[1][1], af[1][2], af[1][3],
                   a_base + 16 * LDAB * 2 + kt * 32);
            uint32_t bf[2][4];
            ldm_x4(bf[0][0], bf[0][1], bf[0][2], bf[0][3], b_base + kt * 32);
            ldm_x4(bf[1][0], bf[1][1], bf[1][2], bf[1][3],
                   b_base + 16 * LDAB * 2 + kt * 32);
#pragma unroll
            for (int mt = 0; mt < 2; ++mt)
#pragma unroll
                for (int nt = 0; nt < 4; ++nt) {
                    uint32_t bb0 = bf[nt >> 1][(nt & 1)];
                    uint32_t bb1 = bf[nt >> 1][(nt & 1) + 2];
                    mma16816(acc[mt][nt][0], acc[mt][nt][1],
                             acc[mt][nt][2], acc[mt][nt][3],
                             af[mt][0], af[mt][1], af[mt][2], af[mt][3], bb0, bb1);
                }
        }
        int nx = g + 3;
        if (nx < NC)
            gemm_issue(P, nph, nx, smb + (nx & 3) * STG_B, bm, bn, tid);
        CP_COMMIT();
    }

    int er = lane >> 2;
    int ec = (lane & 3) * 2;
#pragma unroll
    for (int mt = 0; mt < 2; ++mt)
#pragma unroll
        for (int nt = 0; nt < 4; ++nt) {
            float* dst = Cm + (size_t)(bm + wm * 32 + mt * 16 + er) * ldc
                       + bn + wn * 32 + nt * 8 + ec;
            *(float2*)dst = make_float2(acc[mt][nt][0], acc[mt][nt][1]);
            *(float2*)(dst + 8 * ldc) = make_float2(acc[mt][nt][2], acc[mt][nt][3]);
        }
}

// ---------------------------------------------------------------------------
// Fixed point: x = relu(s*L(R^T x) + Dp.*x + z), 2 columns per warp.
// 256 threads = 8 warps = 16 columns/CTA, grid 128. x0 = relu(z).
// L,R in SMEM row-major [n][k], stride 36 floats (conflict-free float4).
// ---------------------------------------------------------------------------
#define FP_SMEM ((2 * NN * 36 + NN) * 4)

__global__ __launch_bounds__(256, 1)
void fixed_point_kernel(const float* __restrict__ L,
                        const float* __restrict__ R,
                        const float* __restrict__ Dg,
                        __nv_bfloat16* __restrict__ XThi)
{
    extern __shared__ float fsm[];
    float* Ls = fsm;                 // [512][36]
    float* Rs = fsm + NN * 36;
    float* Dp = fsm + 2 * NN * 36;

    int t = threadIdx.x;
    float sD = g_scales[2];
    float s  = g_scales[0] * g_scales[1];

#pragma unroll
    for (int i = 0; i < 64; ++i) {
        int idx = i * 256 + t;
        int n = idx >> 5, k = idx & 31;
        Ls[n * 36 + k] = L[idx];
        Rs[n * 36 + k] = R[idx];
    }
    Dp[t] = Dg[t] * sD;
    Dp[t + 256] = Dg[t + 256] * sD;
    __syncthreads();

    int lane = t & 31;
    int wid  = t >> 5;
    int m0   = blockIdx.x * 16 + wid * 2;

    float x[2][16], z[2][16];
#pragma unroll
    for (int c = 0; c < 2; ++c)
#pragma unroll
        for (int i = 0; i < 16; ++i) {
            z[c][i] = g_ZT[(size_t)(m0 + c) * NN + lane + 32 * i];
            x[c][i] = fmaxf(z[c][i], 0.f);   // first Picard iterate
        }

    for (int iter = 1; iter < MITR; ++iter) {
        float y[2][32];
#pragma unroll
        for (int c = 0; c < 2; ++c)
#pragma unroll
            for (int k = 0; k < 32; ++k) y[c][k] = 0.f;

#pragma unroll
        for (int i = 0; i < 16; ++i) {
            const float* rp = Rs + (lane + 32 * i) * 36;
            float x0 = x[0][i], x1 = x[1][i];
#pragma unroll
            for (int k4 = 0; k4 < 8; ++k4) {
                float4 r = *(const float4*)(rp + k4 * 4);
                y[0][k4 * 4 + 0] = fmaf(r.x, x0, y[0][k4 * 4 + 0]);
                y[0][k4 * 4 + 1] = fmaf(r.y, x0, y[0][k4 * 4 + 1]);
                y[0][k4 * 4 + 2] = fmaf(r.z, x0, y[0][k4 * 4 + 2]);
                y[0][k4 * 4 + 3] = fmaf(r.w, x0, y[0][k4 * 4 + 3]);
                y[1][k4 * 4 + 0] = fmaf(r.x, x1, y[1][k4 * 4 + 0]);
                y[1][k4 * 4 + 1] = fmaf(r.y, x1, y[1][k4 * 4 + 1]);
                y[1][k4 * 4 + 2] = fmaf(r.z, x1, y[1][k4 * 4 + 2]);
                y[1][k4 * 4 + 3] = fmaf(r.w, x1, y[1][k4 * 4 + 3]);
            }
        }
#pragma unroll
        for (int c = 0; c < 2; ++c)
#pragma unroll
            for (int k = 0; k < 32; ++k) {
#pragma unroll
                for (int off = 16; off > 0; off >>= 1)
                    y[c][k] += __shfl_xor_sync(0xffffffffu, y[c][k], off);
                y[c][k] *= s;
            }

        float err = 0.f;
#pragma unroll
        for (int i = 0; i < 16; ++i) {
            int n = lane + 32 * i;
            const float* lp = Ls + n * 36;
            float a0 = fmaf(Dp[n], x[0][i], z[0][i]);
            float a1 = fmaf(Dp[n], x[1][i], z[1][i]);
#pragma unroll
            for (int k4 = 0; k4 < 8; ++k4) {
                float4 l = *(const float4*)(lp + k4 * 4);
                a0 = fmaf(l.x, y[0][k4 * 4 + 0], a0);
                a0 = fmaf(l.y, y[0][k4 * 4 + 1], a0);
                a0 = fmaf(l.z, y[0][k4 * 4 + 2], a0);
                a0 = fmaf(l.w, y[0][k4 * 4 + 3], a0);
                a1 = fmaf(l.x, y[1][k4 * 4 + 0], a1);
                a1 = fmaf(l.y, y[1][k4 * 4 + 1], a1);
                a1 = fmaf(l.z, y[1][k4 * 4 + 2], a1);
                a1 = fmaf(l.w, y[1][k4 * 4 + 3], a1);
            }
            float xn0 = fmaxf(a0, 0.f), xn1 = fmaxf(a1, 0.f);
            err = fmaxf(err, fabsf(xn0 - x[0][i]));
            err = fmaxf(err, fabsf(xn1 - x[1][i]));
            x[0][i] = xn0;
            x[1][i] = xn1;
        }
#pragma unroll
        for (int off = 16; off > 0; off >>= 1)
            err = fmaxf(err, __shfl_xor_sync(0xffffffffu, err, off));
        if (err < TOL) break;
    }

#pragma unroll
    for (int c = 0; c < 2; ++c)
#pragma unroll
        for (int i = 0; i < 16; ++i)
            XThi[(size_t)(m0 + c) * NN + lane + 32 * i] = __float2bfloat16(x[c][i]);
}

// ---------------------------------------------------------------------------
extern "C" void kernel_launch(void* const* d_in, const int* in_sizes, int n_in,
                              void* d_out, int out_size)
{
    (void)in_sizes; (void)n_in; (void)out_size;
    const float* U  = (const float*)d_in[0];
    const float* L  = (const float*)d_in[1];
    const float* R  = (const float*)d_in[2];
    const float* Dg = (const float*)d_in[3];
    const float* B  = (const float*)d_in[4];
    const float* C  = (const float*)d_in[5];
    const float* D  = (const float*)d_in[6];
    float* out = (float*)d_out;

    static int attr_set = 0;
    if (!attr_set) {
        cudaFuncSetAttribute(fixed_point_kernel,
                             cudaFuncAttributeMaxDynamicSharedMemorySize, FP_SMEM);
        cudaFuncSetAttribute(gemm_hmma_kernel,
                             cudaFuncAttributeMaxDynamicSharedMemorySize, GEMM_SMEM);
        attr_set = 1;
    }

    float* zt;  cudaGetSymbolAddress((void**)&zt,  g_ZT);
    __nv_bfloat16 *uhi, *ulo, *bhi, *chi, *dhi, *dlo, *xhi;
    cudaGetSymbolAddress((void**)&uhi, g_Uhi);
    cudaGetSymbolAddress((void**)&ulo, g_Ulo);
    cudaGetSymbolAddress((void**)&bhi, g_Bhi);
    cudaGetSymbolAddress((void**)&chi, g_Chi);
    cudaGetSymbolAddress((void**)&dhi, g_Dhi);
    cudaGetSymbolAddress((void**)&dlo, g_Dlo);
    cudaGetSymbolAddress((void**)&xhi, g_XThi);

    scales_kernel<<<1, 512>>>(L, R, Dg);

    split_all_kernel<<<3328, 256>>>(U, D, B, C, uhi, ulo, dhi, dlo, bhi, chi);

    // ZT = Uhi @ Bhi^T  (single bf16 term; error attenuated ~22x through C)
    {
        GemmParams P{};
        P.A[0] = uhi; P.B[0] = bhi; P.K[0] = PP;
        gemm_hmma_kernel<<<dim3(MM / 64, NN / 64), 128, GEMM_SMEM>>>(P, 1, zt, NN);
    }

    fixed_point_kernel<<<MM / 16, 256, FP_SMEM>>>(L, R, Dg, xhi);

    // out = XThi @ Chi^T + U @ D^T (3-term on the dominant U@D^T)
    {
        GemmParams P{};
        P.A[0] = xhi; P.B[0] = chi; P.K[0] = NN;
        P.A[1] = uhi; P.B[1] = dhi; P.K[1] = PP;
        P.A[2] = ulo; P.B[2] = dhi; P.K[2] = PP;
        P.A[3] = uhi; P.B[3] = dlo; P.K[3] = PP;
        gemm_hmma_kernel<<<dim3(MM / 64, QQ / 64), 128, GEMM_SMEM>>>(P, 4, out, QQ);
    }
}

// round 7
// speedup vs baseline: 5.3045x; 1.3297x over previous
#include <cuda_runtime.h>
#include <cuda_fp16.h>
#include <cstdint>
#include <cmath>

#define NN   512
#define KK   32
#define PP   1024
#define QQ   512
#define MM   2048
#define RHO        0.70710678118654752f
#define KAPPA_DIAG 0.45f
#define TOL        3e-6f
#define MITR       300

// ---------------- device scratch (no allocation) ----------------
__device__ __align__(128) float g_ZT[MM * NN];
__device__ float g_scales[3];

__device__ __align__(128) __half g_Uh[MM * PP];
__device__ __align__(128) __half g_Bh[NN * PP];
__device__ __align__(128) __half g_Ch[QQ * NN];
__device__ __align__(128) __half g_Dh[QQ * PP];
__device__ __align__(128) __half g_Xh[MM * NN];

__device__ __forceinline__ uint32_t smem_u32(const void* p) {
    uint32_t a;
    asm("{ .reg .u64 t; cvta.to.shared.u64 t, %1; cvt.u32.u64 %0, t; }"
        : "=r"(a) : "l"(p));
    return a;
}

__device__ __forceinline__ void ldm_x4(uint32_t& r0, uint32_t& r1,
                                       uint32_t& r2, uint32_t& r3, uint32_t addr) {
    asm volatile("ldmatrix.sync.aligned.m8n8.x4.shared.b16 {%0,%1,%2,%3}, [%4];"
                 : "=r"(r0), "=r"(r1), "=r"(r2), "=r"(r3) : "r"(addr));
}

__device__ __forceinline__ void mma16816(float& c0, float& c1, float& c2, float& c3,
                                         uint32_t a0, uint32_t a1, uint32_t a2, uint32_t a3,
                                         uint32_t b0, uint32_t b1) {
    asm volatile(
        "mma.sync.aligned.m16n8k16.row.col.f32.f16.f16.f32 "
        "{%0,%1,%2,%3}, {%4,%5,%6,%7}, {%8,%9}, {%0,%1,%2,%3};"
        : "+f"(c0), "+f"(c1), "+f"(c2), "+f"(c3)
        : "r"(a0), "r"(a1), "r"(a2), "r"(a3), "r"(b0), "r"(b1));
}

#define CP16(dst, src) \
    asm volatile("cp.async.cg.shared.global [%0], [%1], 16;" :: "r"(dst), "l"(src))
#define CP_COMMIT() asm volatile("cp.async.commit_group;" ::: "memory")
#define CP_WAIT2()  asm volatile("cp.async.wait_group 2;" ::: "memory")

// ---------------------------------------------------------------------------
// Kernel 1: projection scale factors (1 CTA, 512 threads)
// ---------------------------------------------------------------------------
__global__ void scales_kernel(const float* __restrict__ L,
                              const float* __restrict__ R,
                              const float* __restrict__ Dg)
{
    __shared__ float red[NN];
    int t = threadIdx.x;

    float s = 0.f;
#pragma unroll
    for (int k = 0; k < KK; ++k) s += fabsf(L[t * KK + k]);
    red[t] = s;
    __syncthreads();
    for (int h = 256; h > 0; h >>= 1) {
        if (t < h) red[t] = fmaxf(red[t], red[t + h]);
        __syncthreads();
    }
    if (t == 0) {
        float nl = red[0];
        g_scales[0] = (nl > RHO) ? (RHO / nl) : 1.0f;
    }
    __syncthreads();

    {
        int k = t & 31, part = t >> 5;
        float cs = 0.f;
        int n0 = part * 32;
        for (int n = n0; n < n0 + 32; ++n) cs += fabsf(R[n * KK + k]);
        red[t] = cs;
    }
    __syncthreads();
    if (t < 32) {
        float cs = 0.f;
#pragma unroll
        for (int p = 0; p < 16; ++p) cs += red[p * 32 + t];
#pragma unroll
        for (int off = 16; off > 0; off >>= 1)
            cs = fmaxf(cs, __shfl_xor_sync(0xffffffffu, cs, off));
        if (t == 0) g_scales[1] = (cs > RHO) ? (RHO / cs) : 1.0f;
    }
    __syncthreads();

    red[t] = fabsf(Dg[t]);
    __syncthreads();
    for (int h = 256; h > 0; h >>= 1) {
        if (t < h) red[t] = fmaxf(red[t], red[t + h]);
        __syncthreads();
    }
    if (t == 0) {
        float dm = red[0];
        g_scales[2] = (dm > KAPPA_DIAG) ? (KAPPA_DIAG / dm) : 1.0f;
    }
}

// ---------------------------------------------------------------------------
// Fused fp32 -> fp16 conversion for U, D, B, C
// ---------------------------------------------------------------------------
__device__ __forceinline__ void conv_h(const float* src, __half* dst, int i) {
    float4 v = *(const float4*)(src + (size_t)i * 4);
    __half2* hp = (__half2*)(dst + (size_t)i * 4);
    hp[0] = __half2{__float2half_rn(v.x), __float2half_rn(v.y)};
    hp[1] = __half2{__float2half_rn(v.z), __float2half_rn(v.w)};
}

__global__ void convert_all_kernel(const float* __restrict__ U, const float* __restrict__ D,
                                   const float* __restrict__ B, const float* __restrict__ C,
                                   __half* uh, __half* dh, __half* bh, __half* ch)
{
    int b = blockIdx.x, t = threadIdx.x;
    if (b < 2048)       conv_h(U, uh, b * 256 + t);            // 2048*1024/4
    else if (b < 2560)  conv_h(D, dh, (b - 2048) * 256 + t);   // 512*1024/4
    else if (b < 3072)  conv_h(B, bh, (b - 2560) * 256 + t);   // 512*1024/4
    else                conv_h(C, ch, (b - 3072) * 256 + t);   // 512*512/4
}

// ---------------------------------------------------------------------------
// HMMA fp16 GEMM, 64x64x64 tiles, 128 threads (4 warps, 2x2), 4-stage cp.async.
// 2 CTAs/SM. Cm[m][j] = sum over phases sum_k A[m][k]*B[j][k]
// ---------------------------------------------------------------------------
struct GemmParams {
    const __half* A[2];
    const __half* B[2];
    int K[2];    // multiples of 64; also row stride
};

#define LDAB  72                      // fp16 row stride (144B, ldmatrix conflict-free)
#define T_SZB (64 * LDAB * 2)         // 9216 B per operand tile
#define STG_B (2 * T_SZB)             // 18432 B per stage
#define GEMM_SMEM (4 * STG_B)         // 73728 B

__device__ __forceinline__ void gemm_issue(const GemmParams& P, int nph, int chunk,
                                           uint32_t stg, int bm, int bn, int tid)
{
    int c = chunk, ph = 0;
    while (ph < nph - 1 && c >= (P.K[ph] >> 6)) { c -= P.K[ph] >> 6; ++ph; }
    const __half* A = P.A[ph];
    const __half* B = P.B[ph];
    int ld = P.K[ph];
    int kt = c << 6;
#pragma unroll
    for (int i = 0; i < 4; ++i) {
        int idx = tid + 128 * i;
        int row = idx >> 3, c16 = idx & 7;
        CP16(stg + (row * LDAB + c16 * 8) * 2,
             A + (size_t)(bm + row) * ld + kt + c16 * 8);
    }
#pragma unroll
    for (int i = 0; i < 4; ++i) {
        int idx = tid + 128 * i;
        int row = idx >> 3, c16 = idx & 7;
        CP16(stg + T_SZB + (row * LDAB + c16 * 8) * 2,
             B + (size_t)(bn + row) * ld + kt + c16 * 8);
    }
}

__global__ __launch_bounds__(128)
void gemm_hmma_kernel(GemmParams P, int nph, float* __restrict__ Cm, int ldc)
{
    extern __shared__ char gsm[];
    int tid  = threadIdx.x;
    int wid  = tid >> 5;
    int lane = tid & 31;
    int wm   = wid >> 1;   // 0..1
    int wn   = wid & 1;    // 0..1
    int bm = blockIdx.x * 64;
    int bn = blockIdx.y * 64;

    int NC = 0;
#pragma unroll
    for (int i = 0; i < 2; ++i) if (i < nph) NC += P.K[i] >> 6;

    uint32_t smb = smem_u32(gsm);
    int lrow16 = lane & 15;
    int lcol8  = (lane >> 4) << 3;
    uint32_t a_off = ((wm * 32 + lrow16) * LDAB + lcol8) * 2;
    uint32_t b_off = T_SZB + ((wn * 32 + lrow16) * LDAB + lcol8) * 2;

    float acc[2][4][4];
#pragma unroll
    for (int i = 0; i < 2; ++i)
#pragma unroll
        for (int j = 0; j < 4; ++j)
#pragma unroll
            for (int c = 0; c < 4; ++c) acc[i][j][c] = 0.f;

    // prologue: 3 stages in flight
#pragma unroll
    for (int s = 0; s < 3; ++s) {
        if (s < NC) gemm_issue(P, nph, s, smb + s * STG_B, bm, bn, tid);
        CP_COMMIT();
    }

    for (int g = 0; g < NC; ++g) {
        CP_WAIT2();
        __syncthreads();
        int st = g & 3;
        uint32_t a_base = smb + st * STG_B + a_off;
        uint32_t b_base = smb + st * STG_B + b_off;
#pragma unroll
        for (int kt = 0; kt < 4; ++kt) {
            uint32_t af[2][4];
            ldm_x4(af[0][0], af[0][1], af[0][2], af[0][3], a_base + kt * 32);
            ldm_x4(af[1][0], af[1][1], af[1][2], af[1][3],
                   a_base + 16 * LDAB * 2 + kt * 32);
            uint32_t bf[2][4];
            ldm_x4(bf[0][0], bf[0][1], bf[0][2], bf[0][3], b_base + kt * 32);
            ldm_x4(bf[1][0], bf[1][1], bf[1][2], bf[1][3],
                   b_base + 16 * LDAB * 2 + kt * 32);
#pragma unroll
            for (int mt = 0; mt < 2; ++mt)
#pragma unroll
                for (int nt = 0; nt < 4; ++nt) {
                    uint32_t bb0 = bf[nt >> 1][(nt & 1)];
                    uint32_t bb1 = bf[nt >> 1][(nt & 1) + 2];
                    mma16816(acc[mt][nt][0], acc[mt][nt][1],
                             acc[mt][nt][2], acc[mt][nt][3],
                             af[mt][0], af[mt][1], af[mt][2], af[mt][3], bb0, bb1);
                }
        }
        int nx = g + 3;
        if (nx < NC)
            gemm_issue(P, nph, nx, smb + (nx & 3) * STG_B, bm, bn, tid);
        CP_COMMIT();
    }

    int er = lane >> 2;
    int ec = (lane & 3) * 2;
#pragma unroll
    for (int mt = 0; mt < 2; ++mt)
#pragma unroll
        for (int nt = 0; nt < 4; ++nt) {
            float* dst = Cm + (size_t)(bm + wm * 32 + mt * 16 + er) * ldc
                       + bn + wn * 32 + nt * 8 + ec;
            *(float2*)dst = make_float2(acc[mt][nt][0], acc[mt][nt][1]);
            *(float2*)(dst + 8 * ldc) = make_float2(acc[mt][nt][2], acc[mt][nt][3]);
        }
}

// ---------------------------------------------------------------------------
// Fixed point: x = relu(s*L(R^T x) + Dp.*x + z), 2 columns per warp.
// 256 threads = 8 warps = 16 columns/CTA, grid 128. x0 = relu(z).
// L,R in SMEM row-major [n][k], stride 36 floats (conflict-free float4).
// Writes X in fp16 for the output GEMM.
// ---------------------------------------------------------------------------
#define FP_SMEM ((2 * NN * 36 + NN) * 4)

__global__ __launch_bounds__(256, 1)
void fixed_point_kernel(const float* __restrict__ L,
                        const float* __restrict__ R,
                        const float* __restrict__ Dg,
                        __half* __restrict__ Xh)
{
    extern __shared__ float fsm[];
    float* Ls = fsm;                 // [512][36]
    float* Rs = fsm + NN * 36;
    float* Dp = fsm + 2 * NN * 36;

    int t = threadIdx.x;
    float sD = g_scales[2];
    float s  = g_scales[0] * g_scales[1];

#pragma unroll
    for (int i = 0; i < 64; ++i) {
        int idx = i * 256 + t;
        int n = idx >> 5, k = idx & 31;
        Ls[n * 36 + k] = L[idx];
        Rs[n * 36 + k] = R[idx];
    }
    Dp[t] = Dg[t] * sD;
    Dp[t + 256] = Dg[t + 256] * sD;
    __syncthreads();

    int lane = t & 31;
    int wid  = t >> 5;
    int m0   = blockIdx.x * 16 + wid * 2;

    float x[2][16], z[2][16];
#pragma unroll
    for (int c = 0; c < 2; ++c)
#pragma unroll
        for (int i = 0; i < 16; ++i) {
            z[c][i] = g_ZT[(size_t)(m0 + c) * NN + lane + 32 * i];
            x[c][i] = fmaxf(z[c][i], 0.f);   // first Picard iterate
        }

    for (int iter = 1; iter < MITR; ++iter) {
        float y[2][32];
#pragma unroll
        for (int c = 0; c < 2; ++c)
#pragma unroll
            for (int k = 0; k < 32; ++k) y[c][k] = 0.f;

#pragma unroll
        for (int i = 0; i < 16; ++i) {
            const float* rp = Rs + (lane + 32 * i) * 36;
            float x0 = x[0][i], x1 = x[1][i];
#pragma unroll
            for (int k4 = 0; k4 < 8; ++k4) {
                float4 r = *(const float4*)(rp + k4 * 4);
                y[0][k4 * 4 + 0] = fmaf(r.x, x0, y[0][k4 * 4 + 0]);
                y[0][k4 * 4 + 1] = fmaf(r.y, x0, y[0][k4 * 4 + 1]);
                y[0][k4 * 4 + 2] = fmaf(r.z, x0, y[0][k4 * 4 + 2]);
                y[0][k4 * 4 + 3] = fmaf(r.w, x0, y[0][k4 * 4 + 3]);
                y[1][k4 * 4 + 0] = fmaf(r.x, x1, y[1][k4 * 4 + 0]);
                y[1][k4 * 4 + 1] = fmaf(r.y, x1, y[1][k4 * 4 + 1]);
                y[1][k4 * 4 + 2] = fmaf(r.z, x1, y[1][k4 * 4 + 2]);
                y[1][k4 * 4 + 3] = fmaf(r.w, x1, y[1][k4 * 4 + 3]);
            }
        }
#pragma unroll
        for (int c = 0; c < 2; ++c)
#pragma unroll
            for (int k = 0; k < 32; ++k) {
#pragma unroll
                for (int off = 16; off > 0; off >>= 1)
                    y[c][k] += __shfl_xor_sync(0xffffffffu, y[c][k], off);
                y[c][k] *= s;
            }

        float err = 0.f;
#pragma unroll
        for (int i = 0; i < 16; ++i) {
            int n = lane + 32 * i;
            const float* lp = Ls + n * 36;
            float a0 = fmaf(Dp[n], x[0][i], z[0][i]);
            float a1 = fmaf(Dp[n], x[1][i], z[1][i]);
#pragma unroll
            for (int k4 = 0; k4 < 8; ++k4) {
                float4 l = *(const float4*)(lp + k4 * 4);
                a0 = fmaf(l.x, y[0][k4 * 4 + 0], a0);
                a0 = fmaf(l.y, y[0][k4 * 4 + 1], a0);
                a0 = fmaf(l.z, y[0][k4 * 4 + 2], a0);
                a0 = fmaf(l.w, y[0][k4 * 4 + 3], a0);
                a1 = fmaf(l.x, y[1][k4 * 4 + 0], a1);
                a1 = fmaf(l.y, y[1][k4 * 4 + 1], a1);
                a1 = fmaf(l.z, y[1][k4 * 4 + 2], a1);
                a1 = fmaf(l.w, y[1][k4 * 4 + 3], a1);
            }
            float xn0 = fmaxf(a0, 0.f), xn1 = fmaxf(a1, 0.f);
            err = fmaxf(err, fabsf(xn0 - x[0][i]));
            err = fmaxf(err, fabsf(xn1 - x[1][i]));
            x[0][i] = xn0;
            x[1][i] = xn1;
        }
#pragma unroll
        for (int off = 16; off > 0; off >>= 1)
            err = fmaxf(err, __shfl_xor_sync(0xffffffffu, err, off));
        if (err < TOL) break;
    }

#pragma unroll
    for (int c = 0; c < 2; ++c)
#pragma unroll
        for (int i = 0; i < 16; ++i)
            Xh[(size_t)(m0 + c) * NN + lane + 32 * i] = __float2half_rn(x[c][i]);
}

// ---------------------------------------------------------------------------
extern "C" void kernel_launch(void* const* d_in, const int* in_sizes, int n_in,
                              void* d_out, int out_size)
{
    (void)in_sizes; (void)n_in; (void)out_size;
    const float* U  = (const float*)d_in[0];
    const float* L  = (const float*)d_in[1];
    const float* R  = (const float*)d_in[2];
    const float* Dg = (const float*)d_in[3];
    const float* B  = (const float*)d_in[4];
    const float* C  = (const float*)d_in[5];
    const float* D  = (const float*)d_in[6];
    float* out = (float*)d_out;

    static int attr_set = 0;
    if (!attr_set) {
        cudaFuncSetAttribute(fixed_point_kernel,
                             cudaFuncAttributeMaxDynamicSharedMemorySize, FP_SMEM);
        cudaFuncSetAttribute(gemm_hmma_kernel,
                             cudaFuncAttributeMaxDynamicSharedMemorySize, GEMM_SMEM);
        attr_set = 1;
    }

    float* zt;  cudaGetSymbolAddress((void**)&zt,  g_ZT);
    __half *uh, *bh, *ch, *dh, *xh;
    cudaGetSymbolAddress((void**)&uh, g_Uh);
    cudaGetSymbolAddress((void**)&bh, g_Bh);
    cudaGetSymbolAddress((void**)&ch, g_Ch);
    cudaGetSymbolAddress((void**)&dh, g_Dh);
    cudaGetSymbolAddress((void**)&xh, g_Xh);

    scales_kernel<<<1, 512>>>(L, R, Dg);

    convert_all_kernel<<<3328, 256>>>(U, D, B, C, uh, dh, bh, ch);

    // ZT = Uh @ Bh^T  (single fp16 term; error attenuated ~24x through C)
    {
        GemmParams P{};
        P.A[0] = uh; P.B[0] = bh; P.K[0] = PP;
        gemm_hmma_kernel<<<dim3(MM / 64, NN / 64), 128, GEMM_SMEM>>>(P, 1, zt, NN);
    }

    fixed_point_kernel<<<MM / 16, 256, FP_SMEM>>>(L, R, Dg, xh);

    // out = Xh @ Ch^T + Uh @ Dh^T  (single fp16 terms)
    {
        GemmParams P{};
        P.A[0] = xh; P.B[0] = ch; P.K[0] = NN;
        P.A[1] = uh; P.B[1] = dh; P.K[1] = PP;
        gemm_hmma_kernel<<<dim3(MM / 64, QQ / 64), 128, GEMM_SMEM>>>(P, 2, out, QQ);
    }
}

// round 8
// speedup vs baseline: 6.6124x; 1.2466x over previous
#include <cuda_runtime.h>
#include <cuda_fp16.h>
#include <cstdint>
#include <cmath>

#define NN   512
#define KK   32
#define PP   1024
#define QQ   512
#define MM   2048
#define RHO        0.70710678118654752f
#define KAPPA_DIAG 0.45f
#define FP_ITERS   24
#define FP_TOL     3e-4f

// ---------------- device scratch (no allocation) ----------------
__device__ __align__(128) float g_ZT[MM * NN];
__device__ float g_scales[3];

__device__ __align__(128) __half g_Uh[MM * PP];
__device__ __align__(128) __half g_Bh[NN * PP];
__device__ __align__(128) __half g_Ch[QQ * NN];
__device__ __align__(128) __half g_Dh[QQ * PP];
__device__ __align__(128) __half g_Xh[MM * NN];

__device__ __forceinline__ uint32_t smem_u32(const void* p) {
    uint32_t a;
    asm("{ .reg .u64 t; cvta.to.shared.u64 t, %1; cvt.u32.u64 %0, t; }"
        : "=r"(a) : "l"(p));
    return a;
}

__device__ __forceinline__ void ldm_x4(uint32_t& r0, uint32_t& r1,
                                       uint32_t& r2, uint32_t& r3, uint32_t addr) {
    asm volatile("ldmatrix.sync.aligned.m8n8.x4.shared.b16 {%0,%1,%2,%3}, [%4];"
                 : "=r"(r0), "=r"(r1), "=r"(r2), "=r"(r3) : "r"(addr));
}

__device__ __forceinline__ void mma16816(float& c0, float& c1, float& c2, float& c3,
                                         uint32_t a0, uint32_t a1, uint32_t a2, uint32_t a3,
                                         uint32_t b0, uint32_t b1) {
    asm volatile(
        "mma.sync.aligned.m16n8k16.row.col.f32.f16.f16.f32 "
        "{%0,%1,%2,%3}, {%4,%5,%6,%7}, {%8,%9}, {%0,%1,%2,%3};"
        : "+f"(c0), "+f"(c1), "+f"(c2), "+f"(c3)
        : "r"(a0), "r"(a1), "r"(a2), "r"(a3), "r"(b0), "r"(b1));
}

#define CP16(dst, src) \
    asm volatile("cp.async.cg.shared.global [%0], [%1], 16;" :: "r"(dst), "l"(src))
#define CP_COMMIT() asm volatile("cp.async.commit_group;" ::: "memory")
#define CP_WAIT2()  asm volatile("cp.async.wait_group 2;" ::: "memory")

// ---------------------------------------------------------------------------
// Fused convert + scales kernel.
// Blocks 0..3327: fp32->fp16 convert of U, D, B, C.
// Block 3328: L inf-norm scale; 3329: R^T inf-norm scale; 3330: Diag scale.
// ---------------------------------------------------------------------------
__device__ __forceinline__ void conv_h(const float* src, __half* dst, int i) {
    float4 v = *(const float4*)(src + (size_t)i * 4);
    __half2* hp = (__half2*)(dst + (size_t)i * 4);
    hp[0] = __half2{__float2half_rn(v.x), __float2half_rn(v.y)};
    hp[1] = __half2{__float2half_rn(v.z), __float2half_rn(v.w)};
}

__global__ void convert_scales_kernel(const float* __restrict__ U, const float* __restrict__ D,
                                      const float* __restrict__ B, const float* __restrict__ C,
                                      const float* __restrict__ L, const float* __restrict__ R,
                                      const float* __restrict__ Dg,
                                      __half* uh, __half* dh, __half* bh, __half* ch)
{
    int b = blockIdx.x, t = threadIdx.x;
    if (b < 2048)      { conv_h(U, uh, b * 256 + t); return; }
    if (b < 2560)      { conv_h(D, dh, (b - 2048) * 256 + t); return; }
    if (b < 3072)      { conv_h(B, bh, (b - 2560) * 256 + t); return; }
    if (b < 3328)      { conv_h(C, ch, (b - 3072) * 256 + t); return; }

    __shared__ float red[256];
    if (b == 3328) {                    // ||L||_inf = max row sum
        float s0 = 0.f, s1 = 0.f;
#pragma unroll
        for (int k = 0; k < KK; ++k) {
            s0 += fabsf(L[t * KK + k]);
            s1 += fabsf(L[(t + 256) * KK + k]);
        }
        red[t] = fmaxf(s0, s1);
        __syncthreads();
        for (int h = 128; h > 0; h >>= 1) {
            if (t < h) red[t] = fmaxf(red[t], red[t + h]);
            __syncthreads();
        }
        if (t == 0) {
            float nl = red[0];
            g_scales[0] = (nl > RHO) ? (RHO / nl) : 1.0f;
        }
    } else if (b == 3329) {             // ||R^T||_inf = max col sum of R
        int k = t & 31, part = t >> 5;  // 8 parts x 64 rows
        float cs = 0.f;
        int n0 = part * 64;
        for (int n = n0; n < n0 + 64; ++n) cs += fabsf(R[n * KK + k]);
        red[t] = cs;
        __syncthreads();
        if (t < 32) {
            float tot = 0.f;
#pragma unroll
            for (int p = 0; p < 8; ++p) tot += red[p * 32 + t];
#pragma unroll
            for (int off = 16; off > 0; off >>= 1)
                tot = fmaxf(tot, __shfl_xor_sync(0xffffffffu, tot, off));
            if (t == 0) g_scales[1] = (tot > RHO) ? (RHO / tot) : 1.0f;
        }
    } else {                            // max |Diag|
        red[t] = fmaxf(fabsf(Dg[t]), fabsf(Dg[t + 256]));
        __syncthreads();
        for (int h = 128; h > 0; h >>= 1) {
            if (t < h) red[t] = fmaxf(red[t], red[t + h]);
            __syncthreads();
        }
        if (t == 0) {
            float dm = red[0];
            g_scales[2] = (dm > KAPPA_DIAG) ? (KAPPA_DIAG / dm) : 1.0f;
        }
    }
}

// ---------------------------------------------------------------------------
// HMMA fp16 GEMM, 64x64x64 tiles, 128 threads (4 warps, 2x2), 4-stage cp.async.
// 2 CTAs/SM. Cm[m][j] = sum over phases sum_k A[m][k]*B[j][k]
// ---------------------------------------------------------------------------
struct GemmParams {
    const __half* A[2];
    const __half* B[2];
    int K[2];    // multiples of 64; also row stride
};

#define LDAB  72
#define T_SZB (64 * LDAB * 2)
#define STG_B (2 * T_SZB)
#define GEMM_SMEM (4 * STG_B)

__device__ __forceinline__ void gemm_issue(const GemmParams& P, int nph, int chunk,
                                           uint32_t stg, int bm, int bn, int tid)
{
    int c = chunk, ph = 0;
    while (ph < nph - 1 && c >= (P.K[ph] >> 6)) { c -= P.K[ph] >> 6; ++ph; }
    const __half* A = P.A[ph];
    const __half* B = P.B[ph];
    int ld = P.K[ph];
    int kt = c << 6;
#pragma unroll
    for (int i = 0; i < 4; ++i) {
        int idx = tid + 128 * i;
        int row = idx >> 3, c16 = idx & 7;
        CP16(stg + (row * LDAB + c16 * 8) * 2,
             A + (size_t)(bm + row) * ld + kt + c16 * 8);
    }
#pragma unroll
    for (int i = 0; i < 4; ++i) {
        int idx = tid + 128 * i;
        int row = idx >> 3, c16 = idx & 7;
        CP16(stg + T_SZB + (row * LDAB + c16 * 8) * 2,
             B + (size_t)(bn + row) * ld + kt + c16 * 8);
    }
}

__global__ __launch_bounds__(128)
void gemm_hmma_kernel(GemmParams P, int nph, float* __restrict__ Cm, int ldc)
{
    extern __shared__ char gsm[];
    int tid  = threadIdx.x;
    int wid  = tid >> 5;
    int lane = tid & 31;
    int wm   = wid >> 1;
    int wn   = wid & 1;
    int bm = blockIdx.x * 64;
    int bn = blockIdx.y * 64;

    int NC = 0;
#pragma unroll
    for (int i = 0; i < 2; ++i) if (i < nph) NC += P.K[i] >> 6;

    uint32_t smb = smem_u32(gsm);
    int lrow16 = lane & 15;
    int lcol8  = (lane >> 4) << 3;
    uint32_t a_off = ((wm * 32 + lrow16) * LDAB + lcol8) * 2;
    uint32_t b_off = T_SZB + ((wn * 32 + lrow16) * LDAB + lcol8) * 2;

    float acc[2][4][4];
#pragma unroll
    for (int i = 0; i < 2; ++i)
#pragma unroll
        for (int j = 0; j < 4; ++j)
#pragma unroll
            for (int c = 0; c < 4; ++c) acc[i][j][c] = 0.f;

#pragma unroll
    for (int s = 0; s < 3; ++s) {
        if (s < NC) gemm_issue(P, nph, s, smb + s * STG_B, bm, bn, tid);
        CP_COMMIT();
    }

    for (int g = 0; g < NC; ++g) {
        CP_WAIT2();
        __syncthreads();
        int st = g & 3;
        uint32_t a_base = smb + st * STG_B + a_off;
        uint32_t b_base = smb + st * STG_B + b_off;
#pragma unroll
        for (int kt = 0; kt < 4; ++kt) {
            uint32_t af[2][4];
            ldm_x4(af[0][0], af[0][1], af[0][2], af[0][3], a_base + kt * 32);
            ldm_x4(af[1][0], af[1][1], af[1][2], af[1][3],
                   a_base + 16 * LDAB * 2 + kt * 32);
            uint32_t bf[2][4];
            ldm_x4(bf[0][0], bf[0][1], bf[0][2], bf[0][3], b_base + kt * 32);
            ldm_x4(bf[1][0], bf[1][1], bf[1][2], bf[1][3],
                   b_base + 16 * LDAB * 2 + kt * 32);
#pragma unroll
            for (int mt = 0; mt < 2; ++mt)
#pragma unroll
                for (int nt = 0; nt < 4; ++nt) {
                    uint32_t bb0 = bf[nt >> 1][(nt & 1)];
                    uint32_t bb1 = bf[nt >> 1][(nt & 1) + 2];
                    mma16816(acc[mt][nt][0], acc[mt][nt][1],
                             acc[mt][nt][2], acc[mt][nt][3],
                             af[mt][0], af[mt][1], af[mt][2], af[mt][3], bb0, bb1);
                }
        }
        int nx = g + 3;
        if (nx < NC)
            gemm_issue(P, nph, nx, smb + (nx & 3) * STG_B, bm, bn, tid);
        CP_COMMIT();
    }

    int er = lane >> 2;
    int ec = (lane & 3) * 2;
#pragma unroll
    for (int mt = 0; mt < 2; ++mt)
#pragma unroll
        for (int nt = 0; nt < 4; ++nt) {
            float* dst = Cm + (size_t)(bm + wm * 32 + mt * 16 + er) * ldc
                       + bn + wn * 32 + nt * 8 + ec;
            *(float2*)dst = make_float2(acc[mt][nt][0], acc[mt][nt][1]);
            *(float2*)(dst + 8 * ldc) = make_float2(acc[mt][nt][2], acc[mt][nt][3]);
        }
}

// ---------------------------------------------------------------------------
// Fixed point v2 (fp16 / HFMA2): x = relu(s*L(R^T x) + Dp.*x + z).
// 256 threads = 8 warps; each warp packs 2 columns into half2 lanes.
// L, R in SMEM as half2 rows of 17 words (34 halves: 32 data + pad) ->
// bank-conflict-free (17*l mod 32 distinct). s folded into R at fill.
// ---------------------------------------------------------------------------
#define FPROW 17                                 // half2 words per row
#define FP_SMEM (2 * NN * FPROW * 4 + NN * 4)    // Ls + Rs + Dph2 = 71680 B

__global__ __launch_bounds__(256, 1)
void fixed_point_kernel(const float* __restrict__ L,
                        const float* __restrict__ R,
                        const float* __restrict__ Dg,
                        __half* __restrict__ Xh)
{
    extern __shared__ __half2 hsm[];
    __half2* Rs   = hsm;                    // [512][17]
    __half2* Ls   = hsm + NN * FPROW;       // [512][17]
    __half2* Dph2 = hsm + 2 * NN * FPROW;   // [512] splatted (d,d)

    int t = threadIdx.x;
    float s  = g_scales[0] * g_scales[1];
    float sD = g_scales[2];

#pragma unroll
    for (int j = 0; j < 32; ++j) {          // 8192 half2 words per matrix
        int idx = j * 256 + t;
        int n = idx >> 4, kw = idx & 15;
        float2 rv = *(const float2*)(R + n * KK + kw * 2);
        Rs[n * FPROW + kw] = __floats2half2_rn(rv.x * s, rv.y * s);
        float2 lv = *(const float2*)(L + n * KK + kw * 2);
        Ls[n * FPROW + kw] = __floats2half2_rn(lv.x, lv.y);
    }
    Dph2[t]       = __float2half2_rn(Dg[t] * sD);
    Dph2[t + 256] = __float2half2_rn(Dg[t + 256] * sD);
    __syncthreads();

    int lane = t & 31;
    int wid  = t >> 5;
    int m0   = blockIdx.x * 16 + wid * 2;

    const __half2 zero2 = __float2half2_rn(0.f);

    __half2 x2[16], z2[16];
#pragma unroll
    for (int i = 0; i < 16; ++i) {
        int n = lane + 32 * i;
        z2[i] = __floats2half2_rn(g_ZT[(size_t)m0 * NN + n],
                                  g_ZT[(size_t)(m0 + 1) * NN + n]);
        x2[i] = __hmax2(z2[i], zero2);       // first Picard iterate
    }

    for (int iter = 1; iter < FP_ITERS; ++iter) {
        // y (k-packed, per column): yk[c][kw] = (y_c[2kw], y_c[2kw+1]) partials
        __half2 yk[2][16];
#pragma unroll
        for (int kw = 0; kw < 16; ++kw) { yk[0][kw] = zero2; yk[1][kw] = zero2; }

#pragma unroll
        for (int i = 0; i < 16; ++i) {
            int n = lane + 32 * i;
            const __half2* rp = Rs + n * FPROW;
            __half2 xs0 = __low2half2(x2[i]);     // (x_c0, x_c0)
            __half2 xs1 = __high2half2(x2[i]);    // (x_c1, x_c1)
#pragma unroll
            for (int kw = 0; kw < 16; ++kw) {
                __half2 rr = rp[kw];
                yk[0][kw] = __hfma2(rr, xs0, yk[0][kw]);
                yk[1][kw] = __hfma2(rr, xs1, yk[1][kw]);
            }
        }
        // butterfly-sum partials across lanes
#pragma unroll
        for (int c = 0; c < 2; ++c)
#pragma unroll
            for (int kw = 0; kw < 16; ++kw) {
                __half2 v = yk[c][kw];
#pragma unroll
                for (int off = 16; off > 0; off >>= 1)
                    v = __hadd2(v, __shfl_xor_sync(0xffffffffu, v, off));
                yk[c][kw] = v;
            }

        // x' = relu(L y + Dp.*x + z)
        __half2 errh = zero2;
#pragma unroll
        for (int i = 0; i < 16; ++i) {
            int n = lane + 32 * i;
            const __half2* lp = Ls + n * FPROW;
            __half2 base = __hfma2(Dph2[n], x2[i], z2[i]);
            __half2 a0 = zero2, a1 = zero2;
#pragma unroll
            for (int kw = 0; kw < 16; ++kw) {
                __half2 ll = lp[kw];
                a0 = __hfma2(ll, yk[0][kw], a0);
                a1 = __hfma2(ll, yk[1][kw], a1);
            }
            __half s0 = __hadd(__low2half(a0), __high2half(a0));
            __half s1 = __hadd(__low2half(a1), __high2half(a1));
            __half2 xn = __hmax2(__hadd2(base, __halves2half2(s0, s1)), zero2);
            errh = __hmax2(errh, __habs2(__hsub2(xn, x2[i])));
            x2[i] = xn;
        }
#pragma unroll
        for (int off = 16; off > 0; off >>= 1)
            errh = __hmax2(errh, __shfl_xor_sync(0xffffffffu, errh, off));
        float e = fmaxf(__low2float(errh), __high2float(errh));
        if (e < FP_TOL) break;
    }

#pragma unroll
    for (int i = 0; i < 16; ++i) {
        int n = lane + 32 * i;
        Xh[(size_t)m0 * NN + n]       = __low2half(x2[i]);
        Xh[(size_t)(m0 + 1) * NN + n] = __high2half(x2[i]);
    }
}

// ---------------------------------------------------------------------------
extern "C" void kernel_launch(void* const* d_in, const int* in_sizes, int n_in,
                              void* d_out, int out_size)
{
    (void)in_sizes; (void)n_in; (void)out_size;
    const float* U  = (const float*)d_in[0];
    const float* L  = (const float*)d_in[1];
    const float* R  = (const float*)d_in[2];
    const float* Dg = (const float*)d_in[3];
    const float* B  = (const float*)d_in[4];
    const float* C  = (const float*)d_in[5];
    const float* D  = (const float*)d_in[6];
    float* out = (float*)d_out;

    static int attr_set = 0;
    if (!attr_set) {
        cudaFuncSetAttribute(fixed_point_kernel,
                             cudaFuncAttributeMaxDynamicSharedMemorySize, FP_SMEM);
        cudaFuncSetAttribute(gemm_hmma_kernel,
                             cudaFuncAttributeMaxDynamicSharedMemorySize, GEMM_SMEM);
        attr_set = 1;
    }

    float* zt;  cudaGetSymbolAddress((void**)&zt,  g_ZT);
    __half *uh, *bh, *ch, *dh, *xh;
    cudaGetSymbolAddress((void**)&uh, g_Uh);
    cudaGetSymbolAddress((void**)&bh, g_Bh);
    cudaGetSymbolAddress((void**)&ch, g_Ch);
    cudaGetSymbolAddress((void**)&dh, g_Dh);
    cudaGetSymbolAddress((void**)&xh, g_Xh);

    // convert U,D,B,C to fp16 + compute projection scales (fused)
    convert_scales_kernel<<<3331, 256>>>(U, D, B, C, L, R, Dg, uh, dh, bh, ch);

    // ZT = Uh @ Bh^T  (single fp16 term; error attenuated ~24x through C)
    {
        GemmParams P{};
        P.A[0] = uh; P.B[0] = bh; P.K[0] = PP;
        gemm_hmma_kernel<<<dim3(MM / 64, NN / 64), 128, GEMM_SMEM>>>(P, 1, zt, NN);
    }

    fixed_point_kernel<<<MM / 16, 256, FP_SMEM>>>(L, R, Dg, xh);

    // out = Xh @ Ch^T + Uh @ Dh^T
    {
        GemmParams P{};
        P.A[0] = xh; P.B[0] = ch; P.K[0] = NN;
        P.A[1] = uh; P.B[1] = dh; P.K[1] = PP;
        gemm_hmma_kernel<<<dim3(MM / 64, QQ / 64), 128, GEMM_SMEM>>>(P, 2, out, QQ);
    }
}

// round 9
// speedup vs baseline: 6.6390x; 1.0040x over previous
#include <cuda_runtime.h>
#include <cuda_fp16.h>
#include <cstdint>
#include <cmath>

#define NN   512
#define KK   32
#define PP   1024
#define QQ   512
#define MM   2048
#define RHO        0.70710678118654752f
#define KAPPA_DIAG 0.45f
#define FP_ITERS   24
#define FP_TOL     3e-4f

// ---------------- device scratch (no allocation) ----------------
__device__ __align__(128) float g_ZT[MM * NN];
__device__ float g_scales[3];

__device__ __align__(128) __half g_Uh[MM * PP];
__device__ __align__(128) __half g_Bh[NN * PP];
__device__ __align__(128) __half g_Ch[QQ * NN];
__device__ __align__(128) __half g_Dh[QQ * PP];
__device__ __align__(128) __half g_Xh[MM * NN];

__device__ __forceinline__ uint32_t smem_u32(const void* p) {
    uint32_t a;
    asm("{ .reg .u64 t; cvta.to.shared.u64 t, %1; cvt.u32.u64 %0, t; }"
        : "=r"(a) : "l"(p));
    return a;
}

__device__ __forceinline__ void ldm_x4(uint32_t& r0, uint32_t& r1,
                                       uint32_t& r2, uint32_t& r3, uint32_t addr) {
    asm volatile("ldmatrix.sync.aligned.m8n8.x4.shared.b16 {%0,%1,%2,%3}, [%4];"
                 : "=r"(r0), "=r"(r1), "=r"(r2), "=r"(r3) : "r"(addr));
}

__device__ __forceinline__ void mma16816(float& c0, float& c1, float& c2, float& c3,
                                         uint32_t a0, uint32_t a1, uint32_t a2, uint32_t a3,
                                         uint32_t b0, uint32_t b1) {
    asm volatile(
        "mma.sync.aligned.m16n8k16.row.col.f32.f16.f16.f32 "
        "{%0,%1,%2,%3}, {%4,%5,%6,%7}, {%8,%9}, {%0,%1,%2,%3};"
        : "+f"(c0), "+f"(c1), "+f"(c2), "+f"(c3)
        : "r"(a0), "r"(a1), "r"(a2), "r"(a3), "r"(b0), "r"(b1));
}

#define CP16(dst, src) \
    asm volatile("cp.async.cg.shared.global [%0], [%1], 16;" :: "r"(dst), "l"(src))
#define CP_COMMIT() asm volatile("cp.async.commit_group;" ::: "memory")
#define CP_WAIT2()  asm volatile("cp.async.wait_group 2;" ::: "memory")
#define CP_WAIT0()  asm volatile("cp.async.wait_group 0;" ::: "memory")

// ---------------------------------------------------------------------------
// Fused convert + scales kernel.
// ---------------------------------------------------------------------------
__device__ __forceinline__ void conv_h(const float* src, __half* dst, int i) {
    float4 v = *(const float4*)(src + (size_t)i * 4);
    __half2* hp = (__half2*)(dst + (size_t)i * 4);
    hp[0] = __half2{__float2half_rn(v.x), __float2half_rn(v.y)};
    hp[1] = __half2{__float2half_rn(v.z), __float2half_rn(v.w)};
}

__global__ void convert_scales_kernel(const float* __restrict__ U, const float* __restrict__ D,
                                      const float* __restrict__ B, const float* __restrict__ C,
                                      const float* __restrict__ L, const float* __restrict__ R,
                                      const float* __restrict__ Dg,
                                      __half* uh, __half* dh, __half* bh, __half* ch)
{
    int b = blockIdx.x, t = threadIdx.x;
    if (b < 2048)      { conv_h(U, uh, b * 256 + t); return; }
    if (b < 2560)      { conv_h(D, dh, (b - 2048) * 256 + t); return; }
    if (b < 3072)      { conv_h(B, bh, (b - 2560) * 256 + t); return; }
    if (b < 3328)      { conv_h(C, ch, (b - 3072) * 256 + t); return; }

    __shared__ float red[256];
    if (b == 3328) {                    // ||L||_inf = max row sum
        float s0 = 0.f, s1 = 0.f;
#pragma unroll
        for (int k = 0; k < KK; ++k) {
            s0 += fabsf(L[t * KK + k]);
            s1 += fabsf(L[(t + 256) * KK + k]);
        }
        red[t] = fmaxf(s0, s1);
        __syncthreads();
        for (int h = 128; h > 0; h >>= 1) {
            if (t < h) red[t] = fmaxf(red[t], red[t + h]);
            __syncthreads();
        }
        if (t == 0) {
            float nl = red[0];
            g_scales[0] = (nl > RHO) ? (RHO / nl) : 1.0f;
        }
    } else if (b == 3329) {             // ||R^T||_inf = max col sum of R
        int k = t & 31, part = t >> 5;
        float cs = 0.f;
        int n0 = part * 64;
        for (int n = n0; n < n0 + 64; ++n) cs += fabsf(R[n * KK + k]);
        red[t] = cs;
        __syncthreads();
        if (t < 32) {
            float tot = 0.f;
#pragma unroll
            for (int p = 0; p < 8; ++p) tot += red[p * 32 + t];
#pragma unroll
            for (int off = 16; off > 0; off >>= 1)
                tot = fmaxf(tot, __shfl_xor_sync(0xffffffffu, tot, off));
            if (t == 0) g_scales[1] = (tot > RHO) ? (RHO / tot) : 1.0f;
        }
    } else {                            // max |Diag|
        red[t] = fmaxf(fabsf(Dg[t]), fabsf(Dg[t + 256]));
        __syncthreads();
        for (int h = 128; h > 0; h >>= 1) {
            if (t < h) red[t] = fmaxf(red[t], red[t + h]);
            __syncthreads();
        }
        if (t == 0) {
            float dm = red[0];
            g_scales[2] = (dm > KAPPA_DIAG) ? (KAPPA_DIAG / dm) : 1.0f;
        }
    }
}

// ---------------------------------------------------------------------------
// HMMA fp16 GEMM, 64x64x64 chunks, 256 threads = 8 warps:
// (kz, wm, wn) — kz in {0,1} splits the chunk K-range; 4 warps/SMSP at
// 2 CTAs/SM hides ldmatrix/mma latency. Epilogue reduces kz halves via SMEM.
// ---------------------------------------------------------------------------
struct GemmParams {
    const __half* A[2];
    const __half* B[2];
    int K[2];    // multiples of 64; also row stride
};

#define LDAB  72
#define T_SZB (64 * LDAB * 2)
#define STG_B (2 * T_SZB)
#define GEMM_SMEM (4 * STG_B)
#define REDW  66                      // fp32 reduction buffer row stride

__device__ __forceinline__ void gemm_issue(const GemmParams& P, int nph, int chunk,
                                           uint32_t stg, int bm, int bn, int tid)
{
    int c = chunk, ph = 0;
    while (ph < nph - 1 && c >= (P.K[ph] >> 6)) { c -= P.K[ph] >> 6; ++ph; }
    const __half* A = P.A[ph];
    const __half* B = P.B[ph];
    int ld = P.K[ph];
    int kt = c << 6;
#pragma unroll
    for (int i = 0; i < 2; ++i) {
        int idx = tid + 256 * i;
        int row = idx >> 3, c16 = idx & 7;
        CP16(stg + (row * LDAB + c16 * 8) * 2,
             A + (size_t)(bm + row) * ld + kt + c16 * 8);
    }
#pragma unroll
    for (int i = 0; i < 2; ++i) {
        int idx = tid + 256 * i;
        int row = idx >> 3, c16 = idx & 7;
        CP16(stg + T_SZB + (row * LDAB + c16 * 8) * 2,
             B + (size_t)(bn + row) * ld + kt + c16 * 8);
    }
}

__global__ __launch_bounds__(256)
void gemm_hmma_kernel(GemmParams P, int nph, float* __restrict__ Cm, int ldc)
{
    extern __shared__ char gsm[];
    int tid  = threadIdx.x;
    int wid  = tid >> 5;
    int lane = tid & 31;
    int kz   = wid >> 2;          // 0..1: K half
    int wm   = (wid >> 1) & 1;    // 0..1
    int wn   = wid & 1;           // 0..1
    int bm = blockIdx.x * 64;
    int bn = blockIdx.y * 64;

    int NC = 0;
#pragma unroll
    for (int i = 0; i < 2; ++i) if (i < nph) NC += P.K[i] >> 6;

    uint32_t smb = smem_u32(gsm);
    int lrow16 = lane & 15;
    int lcol8  = (lane >> 4) << 3;
    uint32_t a_off = ((wm * 32 + lrow16) * LDAB + lcol8) * 2;
    uint32_t b_off = T_SZB + ((wn * 32 + lrow16) * LDAB + lcol8) * 2;
    uint32_t kz_off = kz * 64;    // 2 kt-steps * 16 halves * 2B

    float acc[2][4][4];
#pragma unroll
    for (int i = 0; i < 2; ++i)
#pragma unroll
        for (int j = 0; j < 4; ++j)
#pragma unroll
            for (int c = 0; c < 4; ++c) acc[i][j][c] = 0.f;

#pragma unroll
    for (int s = 0; s < 3; ++s) {
        if (s < NC) gemm_issue(P, nph, s, smb + s * STG_B, bm, bn, tid);
        CP_COMMIT();
    }

    for (int g = 0; g < NC; ++g) {
        CP_WAIT2();
        __syncthreads();
        int st = g & 3;
        uint32_t a_base = smb + st * STG_B + a_off + kz_off;
        uint32_t b_base = smb + st * STG_B + b_off + kz_off;
#pragma unroll
        for (int j = 0; j < 2; ++j) {   // this warp's 2 kt-steps
            uint32_t af[2][4];
            ldm_x4(af[0][0], af[0][1], af[0][2], af[0][3], a_base + j * 32);
            ldm_x4(af[1][0], af[1][1], af[1][2], af[1][3],
                   a_base + 16 * LDAB * 2 + j * 32);
            uint32_t bf[2][4];
            ldm_x4(bf[0][0], bf[0][1], bf[0][2], bf[0][3], b_base + j * 32);
            ldm_x4(bf[1][0], bf[1][1], bf[1][2], bf[1][3],
                   b_base + 16 * LDAB * 2 + j * 32);
#pragma unroll
            for (int mt = 0; mt < 2; ++mt)
#pragma unroll
                for (int nt = 0; nt < 4; ++nt) {
                    uint32_t bb0 = bf[nt >> 1][(nt & 1)];
                    uint32_t bb1 = bf[nt >> 1][(nt & 1) + 2];
                    mma16816(acc[mt][nt][0], acc[mt][nt][1],
                             acc[mt][nt][2], acc[mt][nt][3],
                             af[mt][0], af[mt][1], af[mt][2], af[mt][3], bb0, bb1);
                }
        }
        int nx = g + 3;
        if (nx < NC)
            gemm_issue(P, nph, nx, smb + (nx & 3) * STG_B, bm, bn, tid);
        CP_COMMIT();
    }

    // ---- reduce kz halves through SMEM, then store ----
    CP_WAIT0();
    __syncthreads();                       // all MMA done; smem reusable
    float* red = (float*)gsm;              // [64][REDW] fp32 = 16.9 KB
    int er = lane >> 2;
    int ec = (lane & 3) * 2;

    if (kz == 1) {
#pragma unroll
        for (int mt = 0; mt < 2; ++mt)
#pragma unroll
            for (int nt = 0; nt < 4; ++nt) {
                float* p = red + (wm * 32 + mt * 16 + er) * REDW + wn * 32 + nt * 8 + ec;
                *(float2*)p = make_float2(acc[mt][nt][0], acc[mt][nt][1]);
                *(float2*)(p + 8 * REDW) = make_float2(acc[mt][nt][2], acc[mt][nt][3]);
            }
    }
    __syncthreads();
    if (kz == 0) {
#pragma unroll
        for (int mt = 0; mt < 2; ++mt)
#pragma unroll
            for (int nt = 0; nt < 4; ++nt) {
                float* p = red + (wm * 32 + mt * 16 + er) * REDW + wn * 32 + nt * 8 + ec;
                float2 o0 = *(float2*)p;
                float2 o1 = *(float2*)(p + 8 * REDW);
                float* dst = Cm + (size_t)(bm + wm * 32 + mt * 16 + er) * ldc
                           + bn + wn * 32 + nt * 8 + ec;
                *(float2*)dst = make_float2(acc[mt][nt][0] + o0.x,
                                            acc[mt][nt][1] + o0.y);
                *(float2*)(dst + 8 * ldc) = make_float2(acc[mt][nt][2] + o1.x,
                                                        acc[mt][nt][3] + o1.y);
            }
    }
}

// ---------------------------------------------------------------------------
// Fixed point (fp16 / HFMA2): x = relu(s*L(R^T x) + Dp.*x + z).
// ---------------------------------------------------------------------------
#define FPROW 17
#define FP_SMEM (2 * NN * FPROW * 4 + NN * 4)

__global__ __launch_bounds__(256, 1)
void fixed_point_kernel(const float* __restrict__ L,
                        const float* __restrict__ R,
                        const float* __restrict__ Dg,
                        __half* __restrict__ Xh)
{
    extern __shared__ __half2 hsm[];
    __half2* Rs   = hsm;
    __half2* Ls   = hsm + NN * FPROW;
    __half2* Dph2 = hsm + 2 * NN * FPROW;

    int t = threadIdx.x;
    float s  = g_scales[0] * g_scales[1];
    float sD = g_scales[2];

#pragma unroll
    for (int j = 0; j < 32; ++j) {
        int idx = j * 256 + t;
        int n = idx >> 4, kw = idx & 15;
        float2 rv = *(const float2*)(R + n * KK + kw * 2);
        Rs[n * FPROW + kw] = __floats2half2_rn(rv.x * s, rv.y * s);
        float2 lv = *(const float2*)(L + n * KK + kw * 2);
        Ls[n * FPROW + kw] = __floats2half2_rn(lv.x, lv.y);
    }
    Dph2[t]       = __float2half2_rn(Dg[t] * sD);
    Dph2[t + 256] = __float2half2_rn(Dg[t + 256] * sD);
    __syncthreads();

    int lane = t & 31;
    int wid  = t >> 5;
    int m0   = blockIdx.x * 16 + wid * 2;

    const __half2 zero2 = __float2half2_rn(0.f);

    __half2 x2[16], z2[16];
#pragma unroll
    for (int i = 0; i < 16; ++i) {
        int n = lane + 32 * i;
        z2[i] = __floats2half2_rn(g_ZT[(size_t)m0 * NN + n],
                                  g_ZT[(size_t)(m0 + 1) * NN + n]);
        x2[i] = __hmax2(z2[i], zero2);
    }

    for (int iter = 1; iter < FP_ITERS; ++iter) {
        __half2 yk[2][16];
#pragma unroll
        for (int kw = 0; kw < 16; ++kw) { yk[0][kw] = zero2; yk[1][kw] = zero2; }

#pragma unroll
        for (int i = 0; i < 16; ++i) {
            int n = lane + 32 * i;
            const __half2* rp = Rs + n * FPROW;
            __half2 xs0 = __low2half2(x2[i]);
            __half2 xs1 = __high2half2(x2[i]);
#pragma unroll
            for (int kw = 0; kw < 16; ++kw) {
                __half2 rr = rp[kw];
                yk[0][kw] = __hfma2(rr, xs0, yk[0][kw]);
                yk[1][kw] = __hfma2(rr, xs1, yk[1][kw]);
            }
        }
#pragma unroll
        for (int c = 0; c < 2; ++c)
#pragma unroll
            for (int kw = 0; kw < 16; ++kw) {
                __half2 v = yk[c][kw];
#pragma unroll
                for (int off = 16; off > 0; off >>= 1)
                    v = __hadd2(v, __shfl_xor_sync(0xffffffffu, v, off));
                yk[c][kw] = v;
            }

        __half2 errh = zero2;
#pragma unroll
        for (int i = 0; i < 16; ++i) {
            int n = lane + 32 * i;
            const __half2* lp = Ls + n * FPROW;
            __half2 base = __hfma2(Dph2[n], x2[i], z2[i]);
            __half2 a0 = zero2, a1 = zero2;
#pragma unroll
            for (int kw = 0; kw < 16; ++kw) {
                __half2 ll = lp[kw];
                a0 = __hfma2(ll, yk[0][kw], a0);
                a1 = __hfma2(ll, yk[1][kw], a1);
            }
            __half s0 = __hadd(__low2half(a0), __high2half(a0));
            __half s1 = __hadd(__low2half(a1), __high2half(a1));
            __half2 xn = __hmax2(__hadd2(base, __halves2half2(s0, s1)), zero2);
            errh = __hmax2(errh, __habs2(__hsub2(xn, x2[i])));
            x2[i] = xn;
        }
#pragma unroll
        for (int off = 16; off > 0; off >>= 1)
            errh = __hmax2(errh, __shfl_xor_sync(0xffffffffu, errh, off));
        float e = fmaxf(__low2float(errh), __high2float(errh));
        if (e < FP_TOL) break;
    }

#pragma unroll
    for (int i = 0; i < 16; ++i) {
        int n = lane + 32 * i;
        Xh[(size_t)m0 * NN + n]       = __low2half(x2[i]);
        Xh[(size_t)(m0 + 1) * NN + n] = __high2half(x2[i]);
    }
}

// ---------------------------------------------------------------------------
extern "C" void kernel_launch(void* const* d_in, const int* in_sizes, int n_in,
                              void* d_out, int out_size)
{
    (void)in_sizes; (void)n_in; (void)out_size;
    const float* U  = (const float*)d_in[0];
    const float* L  = (const float*)d_in[1];
    const float* R  = (const float*)d_in[2];
    const float* Dg = (const float*)d_in[3];
    const float* B  = (const float*)d_in[4];
    const float* C  = (const float*)d_in[5];
    const float* D  = (const float*)d_in[6];
    float* out = (float*)d_out;

    static int attr_set = 0;
    if (!attr_set) {
        cudaFuncSetAttribute(fixed_point_kernel,
                             cudaFuncAttributeMaxDynamicSharedMemorySize, FP_SMEM);
        cudaFuncSetAttribute(gemm_hmma_kernel,
                             cudaFuncAttributeMaxDynamicSharedMemorySize, GEMM_SMEM);
        attr_set = 1;
    }

    float* zt;  cudaGetSymbolAddress((void**)&zt,  g_ZT);
    __half *uh, *bh, *ch, *dh, *xh;
    cudaGetSymbolAddress((void**)&uh, g_Uh);
    cudaGetSymbolAddress((void**)&bh, g_Bh);
    cudaGetSymbolAddress((void**)&ch, g_Ch);
    cudaGetSymbolAddress((void**)&dh, g_Dh);
    cudaGetSymbolAddress((void**)&xh, g_Xh);

    convert_scales_kernel<<<3331, 256>>>(U, D, B, C, L, R, Dg, uh, dh, bh, ch);

    // ZT = Uh @ Bh^T
    {
        GemmParams P{};
        P.A[0] = uh; P.B[0] = bh; P.K[0] = PP;
        gemm_hmma_kernel<<<dim3(MM / 64, NN / 64), 256, GEMM_SMEM>>>(P, 1, zt, NN);
    }

    fixed_point_kernel<<<MM / 16, 256, FP_SMEM>>>(L, R, Dg, xh);

    // out = Xh @ Ch^T + Uh @ Dh^T
    {
        GemmParams P{};
        P.A[0] = xh; P.B[0] = ch; P.K[0] = NN;
        P.A[1] = uh; P.B[1] = dh; P.K[1] = PP;
        gemm_hmma_kernel<<<dim3(MM / 64, QQ / 64), 256, GEMM_SMEM>>>(P, 2, out, QQ);
    }
}